// round 1
// baseline (speedup 1.0000x reference)
#include <cuda_runtime.h>

// Problem constants
#define B_ 4
#define C_ 64
#define T_ 8
#define X_ 96
#define Y_ 96
#define S_ 9216            // X_*Y_
#define N_ 36864           // B_*S_
#define TS_ 73728          // T_*S_
#define TOTAL_ 18874368    // B_*C_*T_*S_
#define QSZ_ 18874368      // T_*C_*N_
#define CNT_ 294912.0f     // B_*T_*S_  (per-channel BN count)

// -------- scratch (device globals; no runtime allocation) --------
__device__ float g_x[TOTAL_];       // conv0 out -> bn0+leaky out (in place)
__device__ float g_qkv[3 * QSZ_];   // q,k,v in [z][t][c][n] layout
__device__ float g_o[QSZ_];         // attention out, [t][c][n]
__device__ float g_z[TOTAL_];       // x + out_proj(o)  (pre-BN1)
__device__ float g_sum0[128];       // bn0: sum[0:64], sumsq[64:128]
__device__ float g_sum1[128];       // bn1
__device__ float g_coef0[128];      // bn0: A[0:64], B[64:128]
__device__ float g_coef1[128];
__device__ float g_m[B_ * C_ * T_]; // spatial means, [b][c][t]
__device__ float g_kern[B_ * T_ * 25];

__device__ __forceinline__ float lk(float v) { return v >= 0.f ? v : 0.01f * v; }

// ---------------- zero accumulators ----------------
__global__ void k_zero() {
    int i = threadIdx.x;
    if (i < 128) { g_sum0[i] = 0.f; g_sum1[i] = 0.f; }
}

// ---------------- conv0: 1x3x3 conv, C64->C64 ----------------
// block = (xx, t, b); 256 threads: co = tid>>2 (64), yy tile of 24 per thread
__global__ void __launch_bounds__(256) k_conv0(const float* __restrict__ h,
                                               const float* __restrict__ w,
                                               const float* __restrict__ bias) {
    const int xx = blockIdx.x, t = blockIdx.y, b = blockIdx.z;
    const int tid = threadIdx.x;
    const int co = tid >> 2;
    const int yy0 = (tid & 3) * 24;

    __shared__ float sIn[3][98];
    __shared__ float sW[576];

    float acc[24];
#pragma unroll
    for (int j = 0; j < 24; j++) acc[j] = 0.f;

    for (int ci = 0; ci < 64; ci++) {
        if (ci) __syncthreads();
        // input rows xx-1..xx+1 with 1-col halo, zero padded
        for (int e = tid; e < 294; e += 256) {
            int dx = e / 98, col = e - dx * 98;
            int gx = xx + dx - 1, gy = col - 1;
            float v = 0.f;
            if (gx >= 0 && gx < X_ && (unsigned)gy < (unsigned)Y_)
                v = h[((b * C_ + ci) * T_ + t) * S_ + gx * Y_ + gy];
            sIn[dx][col] = v;
        }
        // weights for this ci: all 64 c_out x 9 taps
        for (int e = tid; e < 576; e += 256)
            sW[e] = w[((e / 9) * C_ + ci) * 9 + (e % 9)];
        __syncthreads();

        float wr[9];
#pragma unroll
        for (int kk = 0; kk < 9; kk++) wr[kk] = sW[co * 9 + kk];
#pragma unroll
        for (int dx = 0; dx < 3; dx++) {
            const float* r = sIn[dx];
#pragma unroll
            for (int j = 0; j < 24; j++) {
                float a = acc[j];
                a = fmaf(wr[dx * 3 + 0], r[yy0 + j],     a);
                a = fmaf(wr[dx * 3 + 1], r[yy0 + j + 1], a);
                a = fmaf(wr[dx * 3 + 2], r[yy0 + j + 2], a);
                acc[j] = a;
            }
        }
    }
    const float bv = bias[co];
    const int obase = ((b * C_ + co) * T_ + t) * S_ + xx * Y_ + yy0;
#pragma unroll
    for (int j = 0; j < 24; j++) g_x[obase + j] = acc[j] + bv;
}

// ---------------- per-channel sum/sumsq ----------------
// block per (b,c,t): 2048 blocks. mode 0: g_x->g_sum0, mode 1: g_z->g_sum1
__global__ void __launch_bounds__(256) k_stats(int mode) {
    const int bid = blockIdx.x;
    const int c = (bid >> 3) & 63;
    const float* p = (mode ? g_z : g_x) + (size_t)bid * S_;
    float* sums = mode ? g_sum1 : g_sum0;

    float s = 0.f, ss = 0.f;
    for (int i = threadIdx.x; i < S_; i += 256) {
        float v = p[i];
        s += v; ss += v * v;
    }
#pragma unroll
    for (int off = 16; off; off >>= 1) {
        s  += __shfl_down_sync(0xffffffffu, s,  off);
        ss += __shfl_down_sync(0xffffffffu, ss, off);
    }
    __shared__ float wa[8], wb[8];
    const int lane = threadIdx.x & 31, wid = threadIdx.x >> 5;
    if (lane == 0) { wa[wid] = s; wb[wid] = ss; }
    __syncthreads();
    if (threadIdx.x == 0) {
        float ts = 0.f, tss = 0.f;
#pragma unroll
        for (int i = 0; i < 8; i++) { ts += wa[i]; tss += wb[i]; }
        atomicAdd(&sums[c], ts);
        atomicAdd(&sums[64 + c], tss);
    }
}

// ---------------- BN coefficients: A = g*rsqrt(var+eps), B = beta - mu*A ----
__global__ void k_coef(int mode, const float* __restrict__ g,
                       const float* __restrict__ beta) {
    const int c = threadIdx.x;
    if (c >= 64) return;
    const float* sums = mode ? g_sum1 : g_sum0;
    float* coef = mode ? g_coef1 : g_coef0;
    const float inv = 1.0f / CNT_;
    float mu = sums[c] * inv;
    float var = sums[64 + c] * inv - mu * mu;
    float A = g[c] * rsqrtf(var + 1e-5f);
    coef[c] = A;
    coef[64 + c] = beta[c] - mu * A;
}

// ---------------- BN0 apply + leaky, in place on g_x (float4) ----------------
__global__ void __launch_bounds__(256) k_bn0_apply() {
    const int i4 = blockIdx.x * 256 + threadIdx.x;  // TOTAL_/4 threads
    const int c = (i4 / (TS_ / 4)) & 63;
    const float A = g_coef0[c], Bv = g_coef0[64 + c];
    float4 v = *reinterpret_cast<float4*>(&g_x[(size_t)i4 * 4]);
    v.x = lk(fmaf(v.x, A, Bv));
    v.y = lk(fmaf(v.y, A, Bv));
    v.z = lk(fmaf(v.z, A, Bv));
    v.w = lk(fmaf(v.w, A, Bv));
    *reinterpret_cast<float4*>(&g_x[(size_t)i4 * 4]) = v;
}

// ---------------- qkv GEMM: OUT[z][t][mo][n] = W[z*64+mo][:] . x[b,:,t,s] ----
// grid: (72 col tiles of 128, 32 bt, 3 z). 256 threads, micro 4m x 8n.
__global__ void __launch_bounds__(256) k_qkv(const float* __restrict__ W,
                                             const float* __restrict__ bias) {
    __shared__ float As[64][64];   // natural [m][k]
    __shared__ float Bs[64][128];  // [k][n]
    const int tid = threadIdx.x;
    const int j0 = blockIdx.x * 128;
    const int bt = blockIdx.y, b = bt >> 3, t = bt & 7;
    const int z = blockIdx.z;
    const int tn = tid & 15, tm = tid >> 4;

    const float* Wz = W + z * 4096;
    for (int e = tid; e < 4096; e += 256)
        (&As[0][0])[e] = Wz[e];
    const float* xb = g_x + ((b * C_) * T_ + t) * S_ + j0;
    for (int e = tid; e < 8192; e += 256)
        Bs[e >> 7][e & 127] = xb[(e >> 7) * TS_ + (e & 127)];
    __syncthreads();

    float acc[4][8];
#pragma unroll
    for (int i = 0; i < 4; i++)
#pragma unroll
        for (int j = 0; j < 8; j++) acc[i][j] = 0.f;

    const int am = tm * 4, bn = tn * 8;
#pragma unroll 4
    for (int k = 0; k < 64; k++) {
        float av[4];
#pragma unroll
        for (int i = 0; i < 4; i++) av[i] = As[am + i][k];
        float4 b0 = *reinterpret_cast<const float4*>(&Bs[k][bn]);
        float4 b1 = *reinterpret_cast<const float4*>(&Bs[k][bn + 4]);
        float bv[8] = {b0.x, b0.y, b0.z, b0.w, b1.x, b1.y, b1.z, b1.w};
#pragma unroll
        for (int i = 0; i < 4; i++)
#pragma unroll
            for (int j = 0; j < 8; j++)
                acc[i][j] = fmaf(av[i], bv[j], acc[i][j]);
    }

    float* outz = g_qkv + (size_t)z * QSZ_;
    const int ncol = b * S_ + j0 + bn;
#pragma unroll
    for (int i = 0; i < 4; i++) {
        const int mo = am + i;
        const float bb = bias[z * 64 + mo];
        float* op = outz + (t * 64 + mo) * N_ + ncol;
#pragma unroll
        for (int j = 0; j < 8; j++) op[j] = acc[i][j] + bb;
    }
}

// ---------------- attention core: per (n, h) thread, T=8, Dh=8 ----------------
__global__ void __launch_bounds__(128) k_attn() {
    const int n = blockIdx.x * 128 + threadIdx.x;
    const int hh = blockIdx.y;
    const int cb = hh * 8;
    const float* qp = g_qkv;
    const float* kp = g_qkv + QSZ_;
    const float* vp = g_qkv + 2 * QSZ_;

    float kk[8][8], vv[8][8];
#pragma unroll
    for (int tt = 0; tt < 8; tt++)
#pragma unroll
        for (int d = 0; d < 8; d++) {
            const int idx = (tt * 64 + cb + d) * N_ + n;
            kk[tt][d] = kp[idx];
            vv[tt][d] = vp[idx];
        }
    const float scale = 0.3535533905932738f;  // 1/sqrt(8)
#pragma unroll
    for (int tq = 0; tq < 8; tq++) {
        float q[8];
#pragma unroll
        for (int d = 0; d < 8; d++)
            q[d] = qp[(tq * 64 + cb + d) * N_ + n] * scale;
        float s[8];
        float mx = -1e30f;
#pragma unroll
        for (int tt = 0; tt < 8; tt++) {
            float a = 0.f;
#pragma unroll
            for (int d = 0; d < 8; d++) a = fmaf(q[d], kk[tt][d], a);
            s[tt] = a;
            mx = fmaxf(mx, a);
        }
        float sum = 0.f;
#pragma unroll
        for (int tt = 0; tt < 8; tt++) { s[tt] = __expf(s[tt] - mx); sum += s[tt]; }
        const float inv = 1.0f / sum;
#pragma unroll
        for (int d = 0; d < 8; d++) {
            float o = 0.f;
#pragma unroll
            for (int tt = 0; tt < 8; tt++) o = fmaf(s[tt], vv[tt][d], o);
            g_o[(tq * 64 + cb + d) * N_ + n] = o * inv;
        }
    }
}

// ---------------- out_proj GEMM + residual: g_z = g_x + Wout @ o + b ----------
__global__ void __launch_bounds__(256) k_outproj(const float* __restrict__ W,
                                                 const float* __restrict__ bias) {
    __shared__ float As[64][64];
    __shared__ float Bs[64][128];
    const int tid = threadIdx.x;
    const int j0 = blockIdx.x * 128;
    const int bt = blockIdx.y, b = bt >> 3, t = bt & 7;
    const int tn = tid & 15, tm = tid >> 4;

    for (int e = tid; e < 4096; e += 256)
        (&As[0][0])[e] = W[e];
    const float* ob = g_o + (t * 64) * N_ + b * S_ + j0;
    for (int e = tid; e < 8192; e += 256)
        Bs[e >> 7][e & 127] = ob[(e >> 7) * N_ + (e & 127)];
    __syncthreads();

    float acc[4][8];
#pragma unroll
    for (int i = 0; i < 4; i++)
#pragma unroll
        for (int j = 0; j < 8; j++) acc[i][j] = 0.f;

    const int am = tm * 4, bn = tn * 8;
#pragma unroll 4
    for (int k = 0; k < 64; k++) {
        float av[4];
#pragma unroll
        for (int i = 0; i < 4; i++) av[i] = As[am + i][k];
        float4 b0 = *reinterpret_cast<const float4*>(&Bs[k][bn]);
        float4 b1 = *reinterpret_cast<const float4*>(&Bs[k][bn + 4]);
        float bv[8] = {b0.x, b0.y, b0.z, b0.w, b1.x, b1.y, b1.z, b1.w};
#pragma unroll
        for (int i = 0; i < 4; i++)
#pragma unroll
            for (int j = 0; j < 8; j++)
                acc[i][j] = fmaf(av[i], bv[j], acc[i][j]);
    }

#pragma unroll
    for (int i = 0; i < 4; i++) {
        const int mo = am + i;
        const float bb = bias[mo];
        const int idx = ((b * C_ + mo) * T_ + t) * S_ + j0 + bn;
#pragma unroll
        for (int j = 0; j < 8; j++)
            g_z[idx + j] = g_x[idx + j] + acc[i][j] + bb;
    }
}

// ---------------- spatial mean of leaky(bn1(z)) per (b,c,t) ----------------
__global__ void __launch_bounds__(256) k_mean() {
    const int bid = blockIdx.x;  // ((b*64+c)*8+t)
    const int c = (bid >> 3) & 63;
    const float A = g_coef1[c], Bv = g_coef1[64 + c];
    const float* p = g_z + (size_t)bid * S_;
    float s = 0.f;
    for (int i = threadIdx.x; i < S_; i += 256)
        s += lk(fmaf(p[i], A, Bv));
#pragma unroll
    for (int off = 16; off; off >>= 1) s += __shfl_down_sync(0xffffffffu, s, off);
    __shared__ float wa[8];
    const int lane = threadIdx.x & 31, wid = threadIdx.x >> 5;
    if (lane == 0) wa[wid] = s;
    __syncthreads();
    if (threadIdx.x == 0) {
        float ts = 0.f;
#pragma unroll
        for (int i = 0; i < 8; i++) ts += wa[i];
        g_m[bid] = ts * (1.0f / (float)S_);
    }
}

// ---------------- per-(b,t) 5x5 kernels from means ----------------
__global__ void k_kern(const float* __restrict__ w1, const float* __restrict__ b1) {
    const int idx = blockIdx.x * 256 + threadIdx.x;  // [b][t][o]
    if (idx >= B_ * T_ * 25) return;
    const int b = idx / (T_ * 25);
    const int r = idx - b * (T_ * 25);
    const int t = r / 25;
    const int o = r - t * 25;
    float a = b1[o];
#pragma unroll 8
    for (int c = 0; c < 64; c++)
        a = fmaf(g_m[(b * C_ + c) * T_ + t], w1[o * 64 + c], a);
    g_kern[(b * T_ + t) * 25 + o] = a;
}

// ---------------- dynamic depthwise 5x5 conv on original h ----------------
__global__ void __launch_bounds__(256) k_dynconv(const float* __restrict__ h,
                                                 float* __restrict__ out) {
    __shared__ float sp[100 * 100];
    __shared__ float sk[25];
    const int bid = blockIdx.x;  // ((b*64+c)*8+t)
    const int b = bid >> 9;
    const int t = bid & 7;
    const int tid = threadIdx.x;
    const float* base = h + (size_t)bid * S_;

    for (int i = tid; i < 10000; i += 256) sp[i] = 0.f;
    if (tid < 25) sk[tid] = g_kern[(b * T_ + t) * 25 + tid];
    __syncthreads();
    for (int i = tid; i < S_; i += 256) {
        const int r = i / 96, col = i - r * 96;
        sp[(r + 2) * 100 + col + 2] = base[i];
    }
    __syncthreads();

    float kr[25];
#pragma unroll
    for (int q = 0; q < 25; q++) kr[q] = sk[q];

    float* ob = out + (size_t)bid * S_;
    for (int i = tid; i < S_; i += 256) {
        const int r = i / 96, col = i - r * 96;
        const float* pp = &sp[r * 100 + col];
        float a = 0.f;
#pragma unroll
        for (int ii = 0; ii < 5; ii++)
#pragma unroll
            for (int jj = 0; jj < 5; jj++)
                a = fmaf(pp[ii * 100 + jj], kr[ii * 5 + jj], a);
        ob[i] = a;
    }
}

// ---------------- launch ----------------
extern "C" void kernel_launch(void* const* d_in, const int* in_sizes, int n_in,
                              void* d_out, int out_size) {
    const float* h       = (const float*)d_in[0];
    const float* conv0_w = (const float*)d_in[1];
    const float* conv0_b = (const float*)d_in[2];
    const float* bn0_g   = (const float*)d_in[3];
    const float* bn0_b   = (const float*)d_in[4];
    const float* bn1_g   = (const float*)d_in[5];
    const float* bn1_b   = (const float*)d_in[6];
    const float* inW     = (const float*)d_in[7];
    const float* inB     = (const float*)d_in[8];
    const float* outW    = (const float*)d_in[9];
    const float* outB    = (const float*)d_in[10];
    const float* c1w     = (const float*)d_in[11];
    const float* c1b     = (const float*)d_in[12];
    float* out = (float*)d_out;

    k_zero<<<1, 128>>>();
    k_conv0<<<dim3(X_, T_, B_), 256>>>(h, conv0_w, conv0_b);
    k_stats<<<B_ * C_ * T_, 256>>>(0);
    k_coef<<<1, 64>>>(0, bn0_g, bn0_b);
    k_bn0_apply<<<TOTAL_ / 4 / 256, 256>>>();
    k_qkv<<<dim3(S_ / 128, B_ * T_, 3), 256>>>(inW, inB);
    k_attn<<<dim3(N_ / 128, 8), 128>>>();
    k_outproj<<<dim3(S_ / 128, B_ * T_), 256>>>(outW, outB);
    k_stats<<<B_ * C_ * T_, 256>>>(1);
    k_coef<<<1, 64>>>(1, bn1_g, bn1_b);
    k_mean<<<B_ * C_ * T_, 256>>>();
    k_kern<<<4, 256>>>(c1w, c1b);
    k_dynconv<<<B_ * C_ * T_, 256>>>(h, out);
}

// round 4
// speedup vs baseline: 1.5178x; 1.5178x over previous
#include <cuda_runtime.h>
#include <cuda_bf16.h>
#include <cstdint>

// Problem constants
#define B_ 4
#define C_ 64
#define T_ 8
#define X_ 96
#define Y_ 96
#define S_ 9216            // X_*Y_
#define N_ 36864           // B_*S_
#define TS_ 73728          // T_*S_
#define TOTAL_ 18874368    // B_*C_*T_*S_
#define QSZ_ 18874368      // T_*C_*N_
#define CNT_ 294912.0f     // B_*T_*S_

// -------- scratch (device globals; no runtime allocation) --------
__device__ float g_x[TOTAL_];       // conv0 raw output (pre-BN0)
__device__ float g_qkv[3 * QSZ_];   // q,k,v in [z][t][c][n] layout
__device__ float g_o[QSZ_];         // attention out, [t][c][n]
__device__ float g_z[TOTAL_];       // bn0leaky(x) + out_proj(o)  (pre-BN1)
__device__ float g_sum0[128];
__device__ float g_sum1[128];
__device__ float g_coef0[128];      // bn0: A[0:64], B[64:128]
__device__ float g_coef1[128];
__device__ float g_m[B_ * C_ * T_];
__device__ float g_kern[B_ * T_ * 25];
__device__ __align__(16) __nv_bfloat16 g_wk[64 * 576];  // [co][k], k = tap*64+ci

__device__ __forceinline__ float lk(float v) { return v >= 0.f ? v : 0.01f * v; }

// ===================== conv0 via mma.sync bf16 implicit GEMM =====================
// smem layout (dynamic): sin [4][98][74] bf16 (58016 B) ; wk [64][584] bf16 (74752 B)
#define SINW 74
#define SIN_ELEMS (4 * 98 * SINW)       // 29008
#define WKS 584
#define SMEM_WK_OFF 58016
#define SMEM_CONV_TOT (58016 + 64 * WKS * 2)   // 132768

// weight prep: g_wk[co*576 + tap*64 + ci] = w[(co*64+ci)*9 + tap]
__global__ void k_wprep(const float* __restrict__ w) {
    int i = blockIdx.x * 256 + threadIdx.x;
    if (i >= 64 * 576) return;
    int co = i / 576, k = i - co * 576;
    int tap = k >> 6, ci = k & 63;
    g_wk[i] = __float2bfloat16(w[(co * 64 + ci) * 9 + tap]);
}

__global__ void __launch_bounds__(256)
k_conv0_mma(const float* __restrict__ h, const float* __restrict__ bias) {
    extern __shared__ char smem[];
    __nv_bfloat16* sin_s = (__nv_bfloat16*)smem;
    __nv_bfloat16* wk_s = (__nv_bfloat16*)(smem + SMEM_WK_OFF);

    const int tid = threadIdx.x, lane = tid & 31, wid = tid >> 5;
    const int ptile = blockIdx.x, bt = blockIdx.y, b = bt >> 3, t = bt & 7;
    const int p0 = ptile * 128, x0 = p0 / 96;

    // --- stage weights: g_wk [co][576] -> wk_s [co][584] (uint4 = 8 bf16) ---
    {
        const uint4* src = (const uint4*)g_wk;        // 4608 uint4
        for (int e = tid; e < 4608; e += 256) {
            int co = e / 72, q = e - co * 72;
            *(uint4*)&wk_s[co * WKS + q * 8] = src[e];
        }
    }
    // --- zero staged input (covers halo padding) ---
    {
        uint4 z = make_uint4(0, 0, 0, 0);
        uint4* sp = (uint4*)sin_s;
        for (int i = tid; i < SIN_ELEMS / 8; i += 256) sp[i] = z;
    }
    __syncthreads();
    // --- stage input rows x0-1 .. x0+2, layout [row][col(98)][ci(74 pad)] ---
    {
        const float* hb = h + (size_t)b * (64 * TS_) + (size_t)t * S_;
        for (int row = 0; row < 4; row++) {
            int gx = x0 - 1 + row;
            if ((unsigned)gx >= 96u) continue;
            const float* hp = hb + (size_t)gx * 96;
            for (int e = tid; e < 6144; e += 256) {
                int ci = e / 96, y = e - ci * 96;
                sin_s[(row * 98 + y + 1) * SINW + ci] =
                    __float2bfloat16(hp[(size_t)ci * TS_ + y]);
            }
        }
    }
    __syncthreads();

    // warp tiling: mg = wid>>1 (pixel group of 32), nh = wid&1 (co half of 32)
    const int mg = wid >> 1, nh = wid & 1;
    const int g = lane >> 2, tg = lane & 3;

    // per-lane row bases for the 4 m rows (2 m-tiles x 2 half-rows)
    int rb[2][2];
#pragma unroll
    for (int mt = 0; mt < 2; mt++)
#pragma unroll
        for (int hf = 0; hf < 2; hf++) {
            int p = mg * 32 + mt * 16 + hf * 8 + g;
            int gp = p0 + p, px = gp / 96, py = gp - px * 96;
            rb[mt][hf] = ((px - x0) * 98 + py) * SINW;
        }

    float acc[2][4][4];
#pragma unroll
    for (int mt = 0; mt < 2; mt++)
#pragma unroll
        for (int nt = 0; nt < 4; nt++)
#pragma unroll
            for (int i = 0; i < 4; i++) acc[mt][nt][i] = 0.f;

#pragma unroll
    for (int tap = 0; tap < 9; tap++) {
        const int dx = tap / 3, dy = tap - dx * 3;
        const int aoff = (dx * 98 + dy) * SINW + tg * 2;
#pragma unroll
        for (int kk = 0; kk < 4; kk++) {
            const int ko = kk * 16;
            uint32_t A[2][4];
#pragma unroll
            for (int mt = 0; mt < 2; mt++) {
                A[mt][0] = *(const uint32_t*)&sin_s[rb[mt][0] + aoff + ko];
                A[mt][1] = *(const uint32_t*)&sin_s[rb[mt][1] + aoff + ko];
                A[mt][2] = *(const uint32_t*)&sin_s[rb[mt][0] + aoff + ko + 8];
                A[mt][3] = *(const uint32_t*)&sin_s[rb[mt][1] + aoff + ko + 8];
            }
            const int kbase = tap * 64 + ko;
#pragma unroll
            for (int nt = 0; nt < 4; nt++) {
                const int co = nh * 32 + nt * 8 + g;
                uint32_t b0 = *(const uint32_t*)&wk_s[co * WKS + kbase + tg * 2];
                uint32_t b1 = *(const uint32_t*)&wk_s[co * WKS + kbase + 8 + tg * 2];
#pragma unroll
                for (int mt = 0; mt < 2; mt++) {
                    asm volatile(
                        "mma.sync.aligned.m16n8k16.row.col.f32.bf16.bf16.f32 "
                        "{%0,%1,%2,%3}, {%4,%5,%6,%7}, {%8,%9}, {%0,%1,%2,%3};"
                        : "+f"(acc[mt][nt][0]), "+f"(acc[mt][nt][1]),
                          "+f"(acc[mt][nt][2]), "+f"(acc[mt][nt][3])
                        : "r"(A[mt][0]), "r"(A[mt][1]), "r"(A[mt][2]), "r"(A[mt][3]),
                          "r"(b0), "r"(b1));
                }
            }
        }
    }

    // writeout: D[m=pixel][n=co] -> g_x[b][co][t][pixel] + bias
    float* ob = g_x + (size_t)b * (64 * TS_) + (size_t)t * S_ + p0;
#pragma unroll
    for (int nt = 0; nt < 4; nt++) {
        const int co0 = nh * 32 + nt * 8 + tg * 2;
        const float bv0 = __ldg(&bias[co0]);
        const float bv1 = __ldg(&bias[co0 + 1]);
#pragma unroll
        for (int mt = 0; mt < 2; mt++) {
            const int pr = mg * 32 + mt * 16 + g;
            ob[(size_t)co0 * TS_ + pr]           = acc[mt][nt][0] + bv0;
            ob[(size_t)(co0 + 1) * TS_ + pr]     = acc[mt][nt][1] + bv1;
            ob[(size_t)co0 * TS_ + pr + 8]       = acc[mt][nt][2] + bv0;
            ob[(size_t)(co0 + 1) * TS_ + pr + 8] = acc[mt][nt][3] + bv1;
        }
    }
}

// ---------------- zero accumulators ----------------
__global__ void k_zero() {
    int i = threadIdx.x;
    if (i < 128) { g_sum0[i] = 0.f; g_sum1[i] = 0.f; }
}

// ---------------- per-channel sum/sumsq ----------------
__global__ void __launch_bounds__(256) k_stats(int mode) {
    const int bid = blockIdx.x;
    const int c = (bid >> 3) & 63;
    const float* p = (mode ? g_z : g_x) + (size_t)bid * S_;
    float* sums = mode ? g_sum1 : g_sum0;

    float s = 0.f, ss = 0.f;
    for (int i = threadIdx.x; i < S_; i += 256) {
        float v = p[i];
        s += v; ss += v * v;
    }
#pragma unroll
    for (int off = 16; off; off >>= 1) {
        s  += __shfl_down_sync(0xffffffffu, s,  off);
        ss += __shfl_down_sync(0xffffffffu, ss, off);
    }
    __shared__ float wa[8], wb[8];
    const int lane = threadIdx.x & 31, wid = threadIdx.x >> 5;
    if (lane == 0) { wa[wid] = s; wb[wid] = ss; }
    __syncthreads();
    if (threadIdx.x == 0) {
        float ts = 0.f, tss = 0.f;
#pragma unroll
        for (int i = 0; i < 8; i++) { ts += wa[i]; tss += wb[i]; }
        atomicAdd(&sums[c], ts);
        atomicAdd(&sums[64 + c], tss);
    }
}

// ---------------- BN coefficients ----------------
__global__ void k_coef(int mode, const float* __restrict__ g,
                       const float* __restrict__ beta) {
    const int c = threadIdx.x;
    if (c >= 64) return;
    const float* sums = mode ? g_sum1 : g_sum0;
    float* coef = mode ? g_coef1 : g_coef0;
    const float inv = 1.0f / CNT_;
    float mu = sums[c] * inv;
    float var = sums[64 + c] * inv - mu * mu;
    float A = g[c] * rsqrtf(var + 1e-5f);
    coef[c] = A;
    coef[64 + c] = beta[c] - mu * A;
}

// ---------------- qkv GEMM (bn0+leaky fused into B-tile load) ----------------
__global__ void __launch_bounds__(256) k_qkv(const float* __restrict__ W,
                                             const float* __restrict__ bias) {
    __shared__ float As[64][64];
    __shared__ float Bs[64][128];
    const int tid = threadIdx.x;
    const int j0 = blockIdx.x * 128;
    const int bt = blockIdx.y, b = bt >> 3, t = bt & 7;
    const int z = blockIdx.z;
    const int tn = tid & 15, tm = tid >> 4;

    const float* Wz = W + z * 4096;
    for (int e = tid; e < 4096; e += 256)
        (&As[0][0])[e] = Wz[e];
    const float* xb = g_x + ((size_t)(b * C_) * T_ + t) * S_ + j0;
    for (int e = tid; e < 8192; e += 256) {
        int k = e >> 7, n = e & 127;
        float v = xb[(size_t)k * TS_ + n];
        Bs[k][n] = lk(fmaf(v, g_coef0[k], g_coef0[64 + k]));
    }
    __syncthreads();

    float acc[4][8];
#pragma unroll
    for (int i = 0; i < 4; i++)
#pragma unroll
        for (int j = 0; j < 8; j++) acc[i][j] = 0.f;

    const int am = tm * 4, bn = tn * 8;
#pragma unroll 4
    for (int k = 0; k < 64; k++) {
        float av[4];
#pragma unroll
        for (int i = 0; i < 4; i++) av[i] = As[am + i][k];
        float4 b0 = *reinterpret_cast<const float4*>(&Bs[k][bn]);
        float4 b1 = *reinterpret_cast<const float4*>(&Bs[k][bn + 4]);
        float bv[8] = {b0.x, b0.y, b0.z, b0.w, b1.x, b1.y, b1.z, b1.w};
#pragma unroll
        for (int i = 0; i < 4; i++)
#pragma unroll
            for (int j = 0; j < 8; j++)
                acc[i][j] = fmaf(av[i], bv[j], acc[i][j]);
    }

    float* outz = g_qkv + (size_t)z * QSZ_;
    const int ncol = b * S_ + j0 + bn;
#pragma unroll
    for (int i = 0; i < 4; i++) {
        const int mo = am + i;
        const float bb = bias[z * 64 + mo];
        float* op = outz + (size_t)(t * 64 + mo) * N_ + ncol;
#pragma unroll
        for (int j = 0; j < 8; j++) op[j] = acc[i][j] + bb;
    }
}

// ---------------- attention core ----------------
__global__ void __launch_bounds__(128) k_attn() {
    const int n = blockIdx.x * 128 + threadIdx.x;
    const int hh = blockIdx.y;
    const int cb = hh * 8;
    const float* qp = g_qkv;
    const float* kp = g_qkv + QSZ_;
    const float* vp = g_qkv + 2 * (size_t)QSZ_;

    float kk[8][8], vv[8][8];
#pragma unroll
    for (int tt = 0; tt < 8; tt++)
#pragma unroll
        for (int d = 0; d < 8; d++) {
            const size_t idx = (size_t)(tt * 64 + cb + d) * N_ + n;
            kk[tt][d] = kp[idx];
            vv[tt][d] = vp[idx];
        }
    const float scale = 0.3535533905932738f;
#pragma unroll
    for (int tq = 0; tq < 8; tq++) {
        float q[8];
#pragma unroll
        for (int d = 0; d < 8; d++)
            q[d] = qp[(size_t)(tq * 64 + cb + d) * N_ + n] * scale;
        float s[8];
        float mx = -1e30f;
#pragma unroll
        for (int tt = 0; tt < 8; tt++) {
            float a = 0.f;
#pragma unroll
            for (int d = 0; d < 8; d++) a = fmaf(q[d], kk[tt][d], a);
            s[tt] = a;
            mx = fmaxf(mx, a);
        }
        float sum = 0.f;
#pragma unroll
        for (int tt = 0; tt < 8; tt++) { s[tt] = __expf(s[tt] - mx); sum += s[tt]; }
        const float inv = 1.0f / sum;
#pragma unroll
        for (int d = 0; d < 8; d++) {
            float o = 0.f;
#pragma unroll
            for (int tt = 0; tt < 8; tt++) o = fmaf(s[tt], vv[tt][d], o);
            g_o[(size_t)(tq * 64 + cb + d) * N_ + n] = o * inv;
        }
    }
}

// ---------------- out_proj GEMM + bn0-applied residual ----------------
__global__ void __launch_bounds__(256) k_outproj(const float* __restrict__ W,
                                                 const float* __restrict__ bias) {
    __shared__ float As[64][64];
    __shared__ float Bs[64][128];
    const int tid = threadIdx.x;
    const int j0 = blockIdx.x * 128;
    const int bt = blockIdx.y, b = bt >> 3, t = bt & 7;
    const int tn = tid & 15, tm = tid >> 4;

    for (int e = tid; e < 4096; e += 256)
        (&As[0][0])[e] = W[e];
    const float* ob = g_o + (size_t)(t * 64) * N_ + b * S_ + j0;
    for (int e = tid; e < 8192; e += 256)
        Bs[e >> 7][e & 127] = ob[(size_t)(e >> 7) * N_ + (e & 127)];
    __syncthreads();

    float acc[4][8];
#pragma unroll
    for (int i = 0; i < 4; i++)
#pragma unroll
        for (int j = 0; j < 8; j++) acc[i][j] = 0.f;

    const int am = tm * 4, bn = tn * 8;
#pragma unroll 4
    for (int k = 0; k < 64; k++) {
        float av[4];
#pragma unroll
        for (int i = 0; i < 4; i++) av[i] = As[am + i][k];
        float4 b0 = *reinterpret_cast<const float4*>(&Bs[k][bn]);
        float4 b1 = *reinterpret_cast<const float4*>(&Bs[k][bn + 4]);
        float bv[8] = {b0.x, b0.y, b0.z, b0.w, b1.x, b1.y, b1.z, b1.w};
#pragma unroll
        for (int i = 0; i < 4; i++)
#pragma unroll
            for (int j = 0; j < 8; j++)
                acc[i][j] = fmaf(av[i], bv[j], acc[i][j]);
    }

#pragma unroll
    for (int i = 0; i < 4; i++) {
        const int mo = am + i;
        const float bb = bias[mo];
        const float A0 = g_coef0[mo], B0 = g_coef0[64 + mo];
        const size_t idx = ((size_t)(b * C_ + mo) * T_ + t) * S_ + j0 + bn;
#pragma unroll
        for (int j = 0; j < 8; j++)
            g_z[idx + j] = lk(fmaf(g_x[idx + j], A0, B0)) + acc[i][j] + bb;
    }
}

// ---------------- spatial mean of leaky(bn1(z)) ----------------
__global__ void __launch_bounds__(256) k_mean() {
    const int bid = blockIdx.x;
    const int c = (bid >> 3) & 63;
    const float A = g_coef1[c], Bv = g_coef1[64 + c];
    const float* p = g_z + (size_t)bid * S_;
    float s = 0.f;
    for (int i = threadIdx.x; i < S_; i += 256)
        s += lk(fmaf(p[i], A, Bv));
#pragma unroll
    for (int off = 16; off; off >>= 1) s += __shfl_down_sync(0xffffffffu, s, off);
    __shared__ float wa[8];
    const int lane = threadIdx.x & 31, wid = threadIdx.x >> 5;
    if (lane == 0) wa[wid] = s;
    __syncthreads();
    if (threadIdx.x == 0) {
        float ts = 0.f;
#pragma unroll
        for (int i = 0; i < 8; i++) ts += wa[i];
        g_m[bid] = ts * (1.0f / (float)S_);
    }
}

// ---------------- per-(b,t) 5x5 kernels ----------------
__global__ void k_kern(const float* __restrict__ w1, const float* __restrict__ b1) {
    const int idx = blockIdx.x * 256 + threadIdx.x;
    if (idx >= B_ * T_ * 25) return;
    const int b = idx / (T_ * 25);
    const int r = idx - b * (T_ * 25);
    const int t = r / 25;
    const int o = r - t * 25;
    float a = b1[o];
#pragma unroll 8
    for (int c = 0; c < 64; c++)
        a = fmaf(g_m[(b * C_ + c) * T_ + t], w1[o * 64 + c], a);
    g_kern[(b * T_ + t) * 25 + o] = a;
}

// ---------------- dynamic depthwise 5x5 conv ----------------
__global__ void __launch_bounds__(256) k_dynconv(const float* __restrict__ h,
                                                 float* __restrict__ out) {
    __shared__ float sp[100 * 100];
    __shared__ float sk[25];
    const int bid = blockIdx.x;
    const int b = bid >> 9;
    const int t = bid & 7;
    const int tid = threadIdx.x;
    const float* base = h + (size_t)bid * S_;

    for (int i = tid; i < 10000; i += 256) sp[i] = 0.f;
    if (tid < 25) sk[tid] = g_kern[(b * T_ + t) * 25 + tid];
    __syncthreads();
    for (int i = tid; i < S_; i += 256) {
        const int r = i / 96, col = i - r * 96;
        sp[(r + 2) * 100 + col + 2] = base[i];
    }
    __syncthreads();

    float kr[25];
#pragma unroll
    for (int q = 0; q < 25; q++) kr[q] = sk[q];

    float* ob = out + (size_t)bid * S_;
    for (int i = tid; i < S_; i += 256) {
        const int r = i / 96, col = i - r * 96;
        const float* pp = &sp[r * 100 + col];
        float a = 0.f;
#pragma unroll
        for (int ii = 0; ii < 5; ii++)
#pragma unroll
            for (int jj = 0; jj < 5; jj++)
                a = fmaf(pp[ii * 100 + jj], kr[ii * 5 + jj], a);
        ob[i] = a;
    }
}

// ---------------- launch ----------------
extern "C" void kernel_launch(void* const* d_in, const int* in_sizes, int n_in,
                              void* d_out, int out_size) {
    const float* h       = (const float*)d_in[0];
    const float* conv0_w = (const float*)d_in[1];
    const float* conv0_b = (const float*)d_in[2];
    const float* bn0_g   = (const float*)d_in[3];
    const float* bn0_b   = (const float*)d_in[4];
    const float* bn1_g   = (const float*)d_in[5];
    const float* bn1_b   = (const float*)d_in[6];
    const float* inW     = (const float*)d_in[7];
    const float* inB     = (const float*)d_in[8];
    const float* outW    = (const float*)d_in[9];
    const float* outB    = (const float*)d_in[10];
    const float* c1w     = (const float*)d_in[11];
    const float* c1b     = (const float*)d_in[12];
    float* out = (float*)d_out;

    cudaFuncSetAttribute(k_conv0_mma, cudaFuncAttributeMaxDynamicSharedMemorySize,
                         SMEM_CONV_TOT);

    k_zero<<<1, 128>>>();
    k_wprep<<<(64 * 576 + 255) / 256, 256>>>(conv0_w);
    k_conv0_mma<<<dim3(S_ / 128, B_ * T_), 256, SMEM_CONV_TOT>>>(h, conv0_b);
    k_stats<<<B_ * C_ * T_, 256>>>(0);
    k_coef<<<1, 64>>>(0, bn0_g, bn0_b);
    k_qkv<<<dim3(S_ / 128, B_ * T_, 3), 256>>>(inW, inB);
    k_attn<<<dim3(N_ / 128, 8), 128>>>();
    k_outproj<<<dim3(S_ / 128, B_ * T_), 256>>>(outW, outB);
    k_stats<<<B_ * C_ * T_, 256>>>(1);
    k_coef<<<1, 64>>>(1, bn1_g, bn1_b);
    k_mean<<<B_ * C_ * T_, 256>>>();
    k_kern<<<4, 256>>>(c1w, c1b);
    k_dynconv<<<B_ * C_ * T_, 256>>>(h, out);
}

// round 5
// speedup vs baseline: 2.3776x; 1.5664x over previous
#include <cuda_runtime.h>
#include <cuda_bf16.h>
#include <cstdint>

// Problem constants
#define B_ 4
#define C_ 64
#define T_ 8
#define X_ 96
#define Y_ 96
#define S_ 9216            // X_*Y_
#define N_ 36864           // B_*S_
#define TS_ 73728          // T_*S_
#define TOTAL_ 18874368    // B_*C_*T_*S_
#define QSZ_ 18874368      // T_*C_*N_
#define CNT_ 294912.0f     // B_*T_*S_

// -------- scratch (device globals; no runtime allocation) --------
__device__ float g_x[TOTAL_];                     // conv0 raw output (pre-BN0)
__device__ __nv_bfloat16 g_qkvh[3 * QSZ_];        // q,k,v bf16, [z][t][c][n]
__device__ __nv_bfloat16 g_oh[QSZ_];              // attention out bf16, [t][c][n]
__device__ float g_z[TOTAL_];                     // residual + out_proj (pre-BN1)
__device__ float g_sum0[128];
__device__ float g_sum1[128];
__device__ float g_coef0[128];                    // bn0: A[0:64], B[64:128]
__device__ float g_coef1[128];
__device__ float g_m[B_ * C_ * T_];
__device__ float g_kern[B_ * T_ * 25];
__device__ __align__(16) __nv_bfloat16 g_wk[64 * 576];   // conv0 [co][k], k=tap*64+ci
__device__ __align__(16) __nv_bfloat16 g_wqkv[192 * 64]; // in_proj bf16
__device__ __align__(16) __nv_bfloat16 g_wout[64 * 64];  // out_proj bf16

__device__ __forceinline__ float lk(float v) { return v >= 0.f ? v : 0.01f * v; }

__device__ __forceinline__ void mma_bf16(float* c, uint32_t a0, uint32_t a1,
                                         uint32_t a2, uint32_t a3,
                                         uint32_t b0, uint32_t b1) {
    asm volatile(
        "mma.sync.aligned.m16n8k16.row.col.f32.bf16.bf16.f32 "
        "{%0,%1,%2,%3}, {%4,%5,%6,%7}, {%8,%9}, {%0,%1,%2,%3};"
        : "+f"(c[0]), "+f"(c[1]), "+f"(c[2]), "+f"(c[3])
        : "r"(a0), "r"(a1), "r"(a2), "r"(a3), "r"(b0), "r"(b1));
}

__device__ __forceinline__ uint32_t packbf(float a, float b) {
    __nv_bfloat162 p = __floats2bfloat162_rn(a, b);
    return *(uint32_t*)&p;
}

// ===================== weight prep =====================
__global__ void k_wprep(const float* __restrict__ w) {
    int i = blockIdx.x * 256 + threadIdx.x;
    if (i >= 64 * 576) return;
    int co = i / 576, k = i - co * 576;
    int tap = k >> 6, ci = k & 63;
    g_wk[i] = __float2bfloat16(w[(co * 64 + ci) * 9 + tap]);
}
__global__ void k_wprep2(const float* __restrict__ inW, const float* __restrict__ outW) {
    int i = blockIdx.x * 256 + threadIdx.x;
    if (i < 192 * 64) g_wqkv[i] = __float2bfloat16(inW[i]);
    if (i < 64 * 64) g_wout[i] = __float2bfloat16(outW[i]);
}

// ===================== conv0 via mma.sync bf16 implicit GEMM =====================
#define SINW 74
#define SIN_ELEMS (4 * 98 * SINW)
#define WKS 584
#define SMEM_WK_OFF 58016
#define SMEM_CONV_TOT (58016 + 64 * WKS * 2)   // 132768

__global__ void __launch_bounds__(256)
k_conv0_mma(const float* __restrict__ h, const float* __restrict__ bias) {
    extern __shared__ char smem[];
    __nv_bfloat16* sin_s = (__nv_bfloat16*)smem;
    __nv_bfloat16* wk_s = (__nv_bfloat16*)(smem + SMEM_WK_OFF);

    const int tid = threadIdx.x, lane = tid & 31, wid = tid >> 5;
    const int ptile = blockIdx.x, bt = blockIdx.y, b = bt >> 3, t = bt & 7;
    const int p0 = ptile * 128, x0 = p0 / 96;

    {
        const uint4* src = (const uint4*)g_wk;
        for (int e = tid; e < 4608; e += 256) {
            int co = e / 72, q = e - co * 72;
            *(uint4*)&wk_s[co * WKS + q * 8] = src[e];
        }
    }
    {
        uint4 z = make_uint4(0, 0, 0, 0);
        uint4* sp = (uint4*)sin_s;
        for (int i = tid; i < SIN_ELEMS / 8; i += 256) sp[i] = z;
    }
    __syncthreads();
    {
        const float* hb = h + (size_t)b * (64 * TS_) + (size_t)t * S_;
        for (int row = 0; row < 4; row++) {
            int gx = x0 - 1 + row;
            if ((unsigned)gx >= 96u) continue;
            const float* hp = hb + (size_t)gx * 96;
            for (int e = tid; e < 6144; e += 256) {
                int ci = e / 96, y = e - ci * 96;
                sin_s[(row * 98 + y + 1) * SINW + ci] =
                    __float2bfloat16(hp[(size_t)ci * TS_ + y]);
            }
        }
    }
    __syncthreads();

    const int mg = wid >> 1, nh = wid & 1;
    const int g = lane >> 2, tg = lane & 3;

    int rb[2][2];
#pragma unroll
    for (int mt = 0; mt < 2; mt++)
#pragma unroll
        for (int hf = 0; hf < 2; hf++) {
            int p = mg * 32 + mt * 16 + hf * 8 + g;
            int gp = p0 + p, px = gp / 96, py = gp - px * 96;
            rb[mt][hf] = ((px - x0) * 98 + py) * SINW;
        }

    float acc[2][4][4];
#pragma unroll
    for (int mt = 0; mt < 2; mt++)
#pragma unroll
        for (int nt = 0; nt < 4; nt++)
#pragma unroll
            for (int i = 0; i < 4; i++) acc[mt][nt][i] = 0.f;

#pragma unroll
    for (int tap = 0; tap < 9; tap++) {
        const int dx = tap / 3, dy = tap - dx * 3;
        const int aoff = (dx * 98 + dy) * SINW + tg * 2;
#pragma unroll
        for (int kk = 0; kk < 4; kk++) {
            const int ko = kk * 16;
            uint32_t A[2][4];
#pragma unroll
            for (int mt = 0; mt < 2; mt++) {
                A[mt][0] = *(const uint32_t*)&sin_s[rb[mt][0] + aoff + ko];
                A[mt][1] = *(const uint32_t*)&sin_s[rb[mt][1] + aoff + ko];
                A[mt][2] = *(const uint32_t*)&sin_s[rb[mt][0] + aoff + ko + 8];
                A[mt][3] = *(const uint32_t*)&sin_s[rb[mt][1] + aoff + ko + 8];
            }
            const int kbase = tap * 64 + ko;
#pragma unroll
            for (int nt = 0; nt < 4; nt++) {
                const int co = nh * 32 + nt * 8 + g;
                uint32_t b0 = *(const uint32_t*)&wk_s[co * WKS + kbase + tg * 2];
                uint32_t b1 = *(const uint32_t*)&wk_s[co * WKS + kbase + 8 + tg * 2];
#pragma unroll
                for (int mt = 0; mt < 2; mt++)
                    mma_bf16(acc[mt][nt], A[mt][0], A[mt][1], A[mt][2], A[mt][3], b0, b1);
            }
        }
    }

    float* ob = g_x + (size_t)b * (64 * TS_) + (size_t)t * S_ + p0;
#pragma unroll
    for (int nt = 0; nt < 4; nt++) {
        const int co0 = nh * 32 + nt * 8 + tg * 2;
        const float bv0 = __ldg(&bias[co0]);
        const float bv1 = __ldg(&bias[co0 + 1]);
#pragma unroll
        for (int mt = 0; mt < 2; mt++) {
            const int pr = mg * 32 + mt * 16 + g;
            ob[(size_t)co0 * TS_ + pr]           = acc[mt][nt][0] + bv0;
            ob[(size_t)(co0 + 1) * TS_ + pr]     = acc[mt][nt][1] + bv1;
            ob[(size_t)co0 * TS_ + pr + 8]       = acc[mt][nt][2] + bv0;
            ob[(size_t)(co0 + 1) * TS_ + pr + 8] = acc[mt][nt][3] + bv1;
        }
    }
}

// ---------------- zero accumulators ----------------
__global__ void k_zero() {
    int i = threadIdx.x;
    if (i < 128) { g_sum0[i] = 0.f; g_sum1[i] = 0.f; }
}

// ---------------- per-channel sum/sumsq ----------------
__global__ void __launch_bounds__(256) k_stats(int mode) {
    const int bid = blockIdx.x;
    const int c = (bid >> 3) & 63;
    const float* p = (mode ? g_z : g_x) + (size_t)bid * S_;
    float* sums = mode ? g_sum1 : g_sum0;

    float s = 0.f, ss = 0.f;
    for (int i = threadIdx.x; i < S_; i += 256) {
        float v = p[i];
        s += v; ss += v * v;
    }
#pragma unroll
    for (int off = 16; off; off >>= 1) {
        s  += __shfl_down_sync(0xffffffffu, s,  off);
        ss += __shfl_down_sync(0xffffffffu, ss, off);
    }
    __shared__ float wa[8], wb[8];
    const int lane = threadIdx.x & 31, wid = threadIdx.x >> 5;
    if (lane == 0) { wa[wid] = s; wb[wid] = ss; }
    __syncthreads();
    if (threadIdx.x == 0) {
        float ts = 0.f, tss = 0.f;
#pragma unroll
        for (int i = 0; i < 8; i++) { ts += wa[i]; tss += wb[i]; }
        atomicAdd(&sums[c], ts);
        atomicAdd(&sums[64 + c], tss);
    }
}

// ---------------- BN coefficients ----------------
__global__ void k_coef(int mode, const float* __restrict__ g,
                       const float* __restrict__ beta) {
    const int c = threadIdx.x;
    if (c >= 64) return;
    const float* sums = mode ? g_sum1 : g_sum0;
    float* coef = mode ? g_coef1 : g_coef0;
    const float inv = 1.0f / CNT_;
    float mu = sums[c] * inv;
    float var = sums[64 + c] * inv - mu * mu;
    float A = g[c] * rsqrtf(var + 1e-5f);
    coef[c] = A;
    coef[64 + c] = beta[c] - mu * A;
}

// ---------------- qkv: bf16 mma, M=192, K=64, N=128-pixel tiles ----------------
__global__ void __launch_bounds__(256) k_qkv_mma(const float* __restrict__ bias) {
    __shared__ __nv_bfloat16 Ws[192 * 72];
    __shared__ __nv_bfloat16 Xt[128 * 72];
    const int tid = threadIdx.x, lane = tid & 31, wid = tid >> 5;
    const int j0 = blockIdx.x * 128;
    const int bt = blockIdx.y, b = bt >> 3, t = bt & 7;

    // stage W [192][64] -> [192][72]
    {
        const uint4* src = (const uint4*)g_wqkv;
        for (int e = tid; e < 1536; e += 256) {
            int co = e >> 3, q = e & 7;
            *(uint4*)&Ws[co * 72 + q * 8] = src[e];
        }
    }
    // stage X^T [pixel][k] with bn0+leaky fused
    {
        const float* xb = g_x + ((size_t)(b * C_) * T_ + t) * S_ + j0;
        for (int e = tid; e < 4096; e += 256) {
            int kp = e >> 7, n = e & 127;
            int k0 = kp * 2;
            float v0 = lk(fmaf(xb[(size_t)k0 * TS_ + n], g_coef0[k0], g_coef0[64 + k0]));
            float v1 = lk(fmaf(xb[(size_t)(k0 + 1) * TS_ + n], g_coef0[k0 + 1], g_coef0[64 + k0 + 1]));
            *(uint32_t*)&Xt[n * 72 + k0] = packbf(v0, v1);
        }
    }
    __syncthreads();

    const int mg = wid >> 1, nh = wid & 1;   // mg: 48 co rows; nh: 64 pixels
    const int g = lane >> 2, tg = lane & 3;

    float acc[3][8][4];
#pragma unroll
    for (int mt = 0; mt < 3; mt++)
#pragma unroll
        for (int nt = 0; nt < 8; nt++)
#pragma unroll
            for (int i = 0; i < 4; i++) acc[mt][nt][i] = 0.f;

#pragma unroll
    for (int kk = 0; kk < 4; kk++) {
        const int ko = kk * 16 + tg * 2;
        uint32_t A[3][4];
#pragma unroll
        for (int mt = 0; mt < 3; mt++) {
            const int r = mg * 48 + mt * 16;
            A[mt][0] = *(const uint32_t*)&Ws[(r + g) * 72 + ko];
            A[mt][1] = *(const uint32_t*)&Ws[(r + g + 8) * 72 + ko];
            A[mt][2] = *(const uint32_t*)&Ws[(r + g) * 72 + ko + 8];
            A[mt][3] = *(const uint32_t*)&Ws[(r + g + 8) * 72 + ko + 8];
        }
#pragma unroll
        for (int nt = 0; nt < 8; nt++) {
            const int np = nh * 64 + nt * 8 + g;
            uint32_t b0 = *(const uint32_t*)&Xt[np * 72 + ko];
            uint32_t b1 = *(const uint32_t*)&Xt[np * 72 + ko + 8];
#pragma unroll
            for (int mt = 0; mt < 3; mt++)
                mma_bf16(acc[mt][nt], A[mt][0], A[mt][1], A[mt][2], A[mt][3], b0, b1);
        }
    }

    // writeout bf16x2: row co -> [z][t][mo][n]
    const int ncol = b * S_ + j0 + (wid & 1) * 64;
#pragma unroll
    for (int mt = 0; mt < 3; mt++) {
        const int co0 = mg * 48 + mt * 16 + g;      // and co0+8
#pragma unroll
        for (int r = 0; r < 2; r++) {
            const int co = co0 + r * 8;
            const int z = co >> 6, mo = co & 63;
            const float bb = __ldg(&bias[co]);
            __nv_bfloat16* op = g_qkvh + (size_t)z * QSZ_ + (size_t)(t * 64 + mo) * N_ + ncol;
#pragma unroll
            for (int nt = 0; nt < 8; nt++) {
                uint32_t pk = packbf(acc[mt][nt][r * 2] + bb, acc[mt][nt][r * 2 + 1] + bb);
                *(uint32_t*)&op[nt * 8 + tg * 2] = pk;
            }
        }
    }
}

// ---------------- attention core (bf16 io) ----------------
__global__ void __launch_bounds__(128) k_attn() {
    const int n = blockIdx.x * 128 + threadIdx.x;
    const int hh = blockIdx.y;
    const int cb = hh * 8;
    const __nv_bfloat16* qp = g_qkvh;
    const __nv_bfloat16* kp = g_qkvh + QSZ_;
    const __nv_bfloat16* vp = g_qkvh + 2 * (size_t)QSZ_;

    float kk[8][8], vv[8][8];
#pragma unroll
    for (int tt = 0; tt < 8; tt++)
#pragma unroll
        for (int d = 0; d < 8; d++) {
            const size_t idx = (size_t)(tt * 64 + cb + d) * N_ + n;
            kk[tt][d] = __bfloat162float(kp[idx]);
            vv[tt][d] = __bfloat162float(vp[idx]);
        }
    const float scale = 0.3535533905932738f;
#pragma unroll
    for (int tq = 0; tq < 8; tq++) {
        float q[8];
#pragma unroll
        for (int d = 0; d < 8; d++)
            q[d] = __bfloat162float(qp[(size_t)(tq * 64 + cb + d) * N_ + n]) * scale;
        float s[8];
        float mx = -1e30f;
#pragma unroll
        for (int tt = 0; tt < 8; tt++) {
            float a = 0.f;
#pragma unroll
            for (int d = 0; d < 8; d++) a = fmaf(q[d], kk[tt][d], a);
            s[tt] = a;
            mx = fmaxf(mx, a);
        }
        float sum = 0.f;
#pragma unroll
        for (int tt = 0; tt < 8; tt++) { s[tt] = __expf(s[tt] - mx); sum += s[tt]; }
        const float inv = 1.0f / sum;
#pragma unroll
        for (int d = 0; d < 8; d++) {
            float o = 0.f;
#pragma unroll
            for (int tt = 0; tt < 8; tt++) o = fmaf(s[tt], vv[tt][d], o);
            g_oh[(size_t)(tq * 64 + cb + d) * N_ + n] = __float2bfloat16(o * inv);
        }
    }
}

// ---------------- out_proj: bf16 mma + fused residual ----------------
__global__ void __launch_bounds__(256) k_outproj_mma(const float* __restrict__ bias) {
    __shared__ __nv_bfloat16 Ws[64 * 72];
    __shared__ __nv_bfloat16 Ot[128 * 72];
    const int tid = threadIdx.x, lane = tid & 31, wid = tid >> 5;
    const int j0 = blockIdx.x * 128;
    const int bt = blockIdx.y, b = bt >> 3, t = bt & 7;

    {
        const uint4* src = (const uint4*)g_wout;
        for (int e = tid; e < 512; e += 256) {
            int co = e >> 3, q = e & 7;
            *(uint4*)&Ws[co * 72 + q * 8] = src[e];
        }
    }
    {
        const __nv_bfloat16* ob = g_oh + (size_t)(t * 64) * N_ + b * S_ + j0;
        for (int e = tid; e < 4096; e += 256) {
            int kp = e >> 7, n = e & 127;
            int k0 = kp * 2;
            __nv_bfloat162 p;
            p.x = ob[(size_t)k0 * N_ + n];
            p.y = ob[(size_t)(k0 + 1) * N_ + n];
            *(uint32_t*)&Ot[n * 72 + k0] = *(uint32_t*)&p;
        }
    }
    __syncthreads();

    const int mg = wid >> 2, ng = wid & 3;   // mg: 32 co; ng: 32 pixels
    const int g = lane >> 2, tg = lane & 3;

    float acc[2][4][4];
#pragma unroll
    for (int mt = 0; mt < 2; mt++)
#pragma unroll
        for (int nt = 0; nt < 4; nt++)
#pragma unroll
            for (int i = 0; i < 4; i++) acc[mt][nt][i] = 0.f;

#pragma unroll
    for (int kk = 0; kk < 4; kk++) {
        const int ko = kk * 16 + tg * 2;
        uint32_t A[2][4];
#pragma unroll
        for (int mt = 0; mt < 2; mt++) {
            const int r = mg * 32 + mt * 16;
            A[mt][0] = *(const uint32_t*)&Ws[(r + g) * 72 + ko];
            A[mt][1] = *(const uint32_t*)&Ws[(r + g + 8) * 72 + ko];
            A[mt][2] = *(const uint32_t*)&Ws[(r + g) * 72 + ko + 8];
            A[mt][3] = *(const uint32_t*)&Ws[(r + g + 8) * 72 + ko + 8];
        }
#pragma unroll
        for (int nt = 0; nt < 4; nt++) {
            const int np = ng * 32 + nt * 8 + g;
            uint32_t b0 = *(const uint32_t*)&Ot[np * 72 + ko];
            uint32_t b1 = *(const uint32_t*)&Ot[np * 72 + ko + 8];
#pragma unroll
            for (int mt = 0; mt < 2; mt++)
                mma_bf16(acc[mt][nt], A[mt][0], A[mt][1], A[mt][2], A[mt][3], b0, b1);
        }
    }

#pragma unroll
    for (int mt = 0; mt < 2; mt++) {
#pragma unroll
        for (int r = 0; r < 2; r++) {
            const int co = mg * 32 + mt * 16 + r * 8 + g;
            const float bb = __ldg(&bias[co]);
            const float A0 = g_coef0[co], B0 = g_coef0[64 + co];
            const size_t rowb = ((size_t)(b * C_ + co) * T_ + t) * S_ + j0;
#pragma unroll
            for (int nt = 0; nt < 4; nt++) {
                const int px = ng * 32 + nt * 8 + tg * 2;
                float2 xv = *(const float2*)&g_x[rowb + px];
                float2 zv;
                zv.x = lk(fmaf(xv.x, A0, B0)) + acc[mt][nt][r * 2] + bb;
                zv.y = lk(fmaf(xv.y, A0, B0)) + acc[mt][nt][r * 2 + 1] + bb;
                *(float2*)&g_z[rowb + px] = zv;
            }
        }
    }
}

// ---------------- spatial mean of leaky(bn1(z)) ----------------
__global__ void __launch_bounds__(256) k_mean() {
    const int bid = blockIdx.x;
    const int c = (bid >> 3) & 63;
    const float A = g_coef1[c], Bv = g_coef1[64 + c];
    const float* p = g_z + (size_t)bid * S_;
    float s = 0.f;
    for (int i = threadIdx.x; i < S_; i += 256)
        s += lk(fmaf(p[i], A, Bv));
#pragma unroll
    for (int off = 16; off; off >>= 1) s += __shfl_down_sync(0xffffffffu, s, off);
    __shared__ float wa[8];
    const int lane = threadIdx.x & 31, wid = threadIdx.x >> 5;
    if (lane == 0) wa[wid] = s;
    __syncthreads();
    if (threadIdx.x == 0) {
        float ts = 0.f;
#pragma unroll
        for (int i = 0; i < 8; i++) ts += wa[i];
        g_m[bid] = ts * (1.0f / (float)S_);
    }
}

// ---------------- per-(b,t) 5x5 kernels ----------------
__global__ void k_kern(const float* __restrict__ w1, const float* __restrict__ b1) {
    const int idx = blockIdx.x * 256 + threadIdx.x;
    if (idx >= B_ * T_ * 25) return;
    const int b = idx / (T_ * 25);
    const int r = idx - b * (T_ * 25);
    const int t = r / 25;
    const int o = r - t * 25;
    float a = b1[o];
#pragma unroll 8
    for (int c = 0; c < 64; c++)
        a = fmaf(g_m[(b * C_ + c) * T_ + t], w1[o * 64 + c], a);
    g_kern[(b * T_ + t) * 25 + o] = a;
}

// ---------------- dynamic depthwise 5x5 conv ----------------
__global__ void __launch_bounds__(256) k_dynconv(const float* __restrict__ h,
                                                 float* __restrict__ out) {
    __shared__ float sp[100 * 100];
    __shared__ float sk[25];
    const int bid = blockIdx.x;
    const int b = bid >> 9;
    const int t = bid & 7;
    const int tid = threadIdx.x;
    const float* base = h + (size_t)bid * S_;

    for (int i = tid; i < 10000; i += 256) sp[i] = 0.f;
    if (tid < 25) sk[tid] = g_kern[(b * T_ + t) * 25 + tid];
    __syncthreads();
    for (int i = tid; i < S_; i += 256) {
        const int r = i / 96, col = i - r * 96;
        sp[(r + 2) * 100 + col + 2] = base[i];
    }
    __syncthreads();

    float kr[25];
#pragma unroll
    for (int q = 0; q < 25; q++) kr[q] = sk[q];

    float* ob = out + (size_t)bid * S_;
    for (int i = tid; i < S_; i += 256) {
        const int r = i / 96, col = i - r * 96;
        const float* pp = &sp[r * 100 + col];
        float a = 0.f;
#pragma unroll
        for (int ii = 0; ii < 5; ii++)
#pragma unroll
            for (int jj = 0; jj < 5; jj++)
                a = fmaf(pp[ii * 100 + jj], kr[ii * 5 + jj], a);
        ob[i] = a;
    }
}

// ---------------- launch ----------------
extern "C" void kernel_launch(void* const* d_in, const int* in_sizes, int n_in,
                              void* d_out, int out_size) {
    const float* h       = (const float*)d_in[0];
    const float* conv0_w = (const float*)d_in[1];
    const float* conv0_b = (const float*)d_in[2];
    const float* bn0_g   = (const float*)d_in[3];
    const float* bn0_b   = (const float*)d_in[4];
    const float* bn1_g   = (const float*)d_in[5];
    const float* bn1_b   = (const float*)d_in[6];
    const float* inW     = (const float*)d_in[7];
    const float* inB     = (const float*)d_in[8];
    const float* outW    = (const float*)d_in[9];
    const float* outB    = (const float*)d_in[10];
    const float* c1w     = (const float*)d_in[11];
    const float* c1b     = (const float*)d_in[12];
    float* out = (float*)d_out;

    cudaFuncSetAttribute(k_conv0_mma, cudaFuncAttributeMaxDynamicSharedMemorySize,
                         SMEM_CONV_TOT);

    k_zero<<<1, 128>>>();
    k_wprep<<<(64 * 576 + 255) / 256, 256>>>(conv0_w);
    k_wprep2<<<(192 * 64 + 255) / 256, 256>>>(inW, outW);
    k_conv0_mma<<<dim3(S_ / 128, B_ * T_), 256, SMEM_CONV_TOT>>>(h, conv0_b);
    k_stats<<<B_ * C_ * T_, 256>>>(0);
    k_coef<<<1, 64>>>(0, bn0_g, bn0_b);
    k_qkv_mma<<<dim3(S_ / 128, B_ * T_), 256>>>(inB);
    k_attn<<<dim3(N_ / 128, 8), 128>>>();
    k_outproj_mma<<<dim3(S_ / 128, B_ * T_), 256>>>(outB);
    k_stats<<<B_ * C_ * T_, 256>>>(1);
    k_coef<<<1, 64>>>(1, bn1_g, bn1_b);
    k_mean<<<B_ * C_ * T_, 256>>>();
    k_kern<<<4, 256>>>(c1w, c1b);
    k_dynconv<<<B_ * C_ * T_, 256>>>(h, out);
}

// round 6
// speedup vs baseline: 2.8683x; 1.2064x over previous
#include <cuda_runtime.h>
#include <cuda_bf16.h>
#include <cstdint>

// Problem constants
#define B_ 4
#define C_ 64
#define T_ 8
#define X_ 96
#define Y_ 96
#define S_ 9216            // X_*Y_
#define N_ 36864           // B_*S_
#define TS_ 73728          // T_*S_
#define TOTAL_ 18874368    // B_*C_*T_*S_
#define QSZ_ 18874368      // T_*C_*N_
#define CNT_ 294912.0f     // B_*T_*S_

// -------- scratch (device globals; no runtime allocation) --------
__device__ float g_x[TOTAL_];                     // conv0 raw output (pre-BN0)
__device__ __nv_bfloat16 g_qkvh[3 * QSZ_];        // q,k,v bf16, [z][t][c][n]
__device__ __nv_bfloat16 g_oh[QSZ_];              // attention out bf16, [t][c][n]
__device__ float g_z[TOTAL_];                     // residual + out_proj (pre-BN1)
__device__ float g_sum0[128];
__device__ float g_sum1[128];
__device__ float g_coef0[128];                    // bn0: A[0:64], B[64:128]
__device__ float g_coef1[128];
__device__ float g_m[B_ * C_ * T_];
__device__ float g_kern[B_ * T_ * 25];
__device__ __align__(16) __nv_bfloat16 g_wk[64 * 576];   // conv0 [co][k], k=tap*64+ci
__device__ __align__(16) __nv_bfloat16 g_wqkv[192 * 64]; // in_proj bf16
__device__ __align__(16) __nv_bfloat16 g_wout[64 * 64];  // out_proj bf16

__device__ __forceinline__ float lk(float v) { return v >= 0.f ? v : 0.01f * v; }

__device__ __forceinline__ void mma_bf16(float* c, uint32_t a0, uint32_t a1,
                                         uint32_t a2, uint32_t a3,
                                         uint32_t b0, uint32_t b1) {
    asm volatile(
        "mma.sync.aligned.m16n8k16.row.col.f32.bf16.bf16.f32 "
        "{%0,%1,%2,%3}, {%4,%5,%6,%7}, {%8,%9}, {%0,%1,%2,%3};"
        : "+f"(c[0]), "+f"(c[1]), "+f"(c[2]), "+f"(c[3])
        : "r"(a0), "r"(a1), "r"(a2), "r"(a3), "r"(b0), "r"(b1));
}

__device__ __forceinline__ uint32_t packbf(float a, float b) {
    __nv_bfloat162 p = __floats2bfloat162_rn(a, b);
    return *(uint32_t*)&p;
}

// ===================== weight prep =====================
__global__ void k_wprep(const float* __restrict__ w) {
    int i = blockIdx.x * 256 + threadIdx.x;
    if (i >= 64 * 576) return;
    int co = i / 576, k = i - co * 576;
    int tap = k >> 6, ci = k & 63;
    g_wk[i] = __float2bfloat16(w[(co * 64 + ci) * 9 + tap]);
}
__global__ void k_wprep2(const float* __restrict__ inW, const float* __restrict__ outW) {
    int i = blockIdx.x * 256 + threadIdx.x;
    if (i < 192 * 64) g_wqkv[i] = __float2bfloat16(inW[i]);
    if (i < 64 * 64) g_wout[i] = __float2bfloat16(outW[i]);
}

// ===================== conv0: persistent multi-tile bf16 mma =====================
#define SINW 74
#define ROWE (98 * SINW)                // 7252 elems per row slot
#define RING 6
#define WKS 584
#define SM_WK_OFF (RING * ROWE * 2)     // 87024 bytes
#define SM_CONV_TOT (SM_WK_OFF + 64 * WKS * 2)   // 161776 bytes

__device__ __forceinline__ void stage_row(__nv_bfloat16* sin_s, const float* hb,
                                          int gx, int tid) {
    const int slot = (gx + 7) % 6;      // == (gx+1) mod 6, gx >= -1
    __nv_bfloat16* dst = sin_s + slot * ROWE;
    if ((unsigned)gx >= 96u) {
        for (int e = tid; e < 6144; e += 256) {
            int ci = e / 96, y = e - ci * 96;
            dst[(y + 1) * SINW + ci] = __float2bfloat16(0.f);
        }
    } else {
        const float* hp = hb + (size_t)gx * 96;
        for (int e = tid; e < 6144; e += 256) {
            int ci = e / 96, y = e - ci * 96;
            dst[(y + 1) * SINW + ci] = __float2bfloat16(hp[(size_t)ci * TS_ + y]);
        }
    }
    // halo columns 0 and 97
    if (tid < 64) dst[tid] = __float2bfloat16(0.f);
    else if (tid < 128) dst[97 * SINW + (tid - 64)] = __float2bfloat16(0.f);
}

__global__ void __launch_bounds__(256)
k_conv0_mma(const float* __restrict__ h, const float* __restrict__ bias) {
    extern __shared__ char smem[];
    __nv_bfloat16* sin_s = (__nv_bfloat16*)smem;
    __nv_bfloat16* wk_s = (__nv_bfloat16*)(smem + SM_WK_OFF);
    __shared__ float s_st[128];

    const int tid = threadIdx.x, lane = tid & 31, wid = tid >> 5;
    const int group = blockIdx.x, bt = blockIdx.y, b = bt >> 3, t = bt & 7;
    const float* hb = h + (size_t)b * (64 * TS_) + (size_t)t * S_;

    if (tid < 128) s_st[tid] = 0.f;
    // stage weights once
    {
        const uint4* src = (const uint4*)g_wk;
        for (int e = tid; e < 4608; e += 256) {
            int co = e / 72, q = e - co * 72;
            *(uint4*)&wk_s[co * WKS + q * 8] = src[e];
        }
    }
    // prologue: rows for first tile
    const int x0f = group * 24;
    for (int gx = x0f - 1; gx <= x0f + 2; gx++) stage_row(sin_s, hb, gx, tid);
    __syncthreads();

    const int mg = wid >> 1, nh = wid & 1;
    const int g = lane >> 2, tg = lane & 3;

    // preload bias values for this thread's 8 channels
    float bv[4][2];
#pragma unroll
    for (int nt = 0; nt < 4; nt++) {
        const int co0 = nh * 32 + nt * 8 + tg * 2;
        bv[nt][0] = __ldg(&bias[co0]);
        bv[nt][1] = __ldg(&bias[co0 + 1]);
    }

    float st_s[8], st_q[8];
#pragma unroll
    for (int i = 0; i < 8; i++) { st_s[i] = 0.f; st_q[i] = 0.f; }

    float* obB = g_x + (size_t)b * (64 * TS_) + (size_t)t * S_;

    for (int ti = 0; ti < 18; ti++) {
        const int p0 = (group * 18 + ti) * 128;
        const int x0 = p0 / 96;
        // stage rows for next tile (disjoint ring slots; overlaps with compute)
        if (ti < 17) {
            const int x0n = (p0 + 128) / 96;
            for (int gx = x0 + 3; gx <= x0n + 2; gx++) stage_row(sin_s, hb, gx, tid);
        }

        // per-lane fragment bases for this tile
        int slotoff[2][2][3];
#pragma unroll
        for (int mt = 0; mt < 2; mt++)
#pragma unroll
            for (int hf = 0; hf < 2; hf++) {
                int p = mg * 32 + mt * 16 + hf * 8 + g;
                int gp = p0 + p, px = gp / 96, py = gp - px * 96;
#pragma unroll
                for (int dx = 0; dx < 3; dx++)
                    slotoff[mt][hf][dx] = ((px + dx) % 6) * ROWE + py * SINW;
            }

        float acc[2][4][4];
#pragma unroll
        for (int mt = 0; mt < 2; mt++)
#pragma unroll
            for (int nt = 0; nt < 4; nt++)
#pragma unroll
                for (int i = 0; i < 4; i++) acc[mt][nt][i] = 0.f;

#pragma unroll
        for (int tap = 0; tap < 9; tap++) {
            const int dx = tap / 3, dy = tap - dx * 3;
            const int cb = dy * SINW + tg * 2;
#pragma unroll
            for (int kk = 0; kk < 4; kk++) {
                const int ko = kk * 16;
                uint32_t A[2][4];
#pragma unroll
                for (int mt = 0; mt < 2; mt++) {
                    A[mt][0] = *(const uint32_t*)&sin_s[slotoff[mt][0][dx] + cb + ko];
                    A[mt][1] = *(const uint32_t*)&sin_s[slotoff[mt][1][dx] + cb + ko];
                    A[mt][2] = *(const uint32_t*)&sin_s[slotoff[mt][0][dx] + cb + ko + 8];
                    A[mt][3] = *(const uint32_t*)&sin_s[slotoff[mt][1][dx] + cb + ko + 8];
                }
                const int kbase = tap * 64 + ko;
#pragma unroll
                for (int nt = 0; nt < 4; nt++) {
                    const int co = nh * 32 + nt * 8 + g;
                    uint32_t b0 = *(const uint32_t*)&wk_s[co * WKS + kbase + tg * 2];
                    uint32_t b1 = *(const uint32_t*)&wk_s[co * WKS + kbase + 8 + tg * 2];
#pragma unroll
                    for (int mt = 0; mt < 2; mt++)
                        mma_bf16(acc[mt][nt], A[mt][0], A[mt][1], A[mt][2], A[mt][3], b0, b1);
                }
            }
        }

        // writeout + BN0 stats accumulation
        float* ob = obB + p0;
#pragma unroll
        for (int nt = 0; nt < 4; nt++) {
            const int co0 = nh * 32 + nt * 8 + tg * 2;
#pragma unroll
            for (int mt = 0; mt < 2; mt++) {
                const int pr = mg * 32 + mt * 16 + g;
                float v0 = acc[mt][nt][0] + bv[nt][0];
                float v1 = acc[mt][nt][1] + bv[nt][1];
                float v2 = acc[mt][nt][2] + bv[nt][0];
                float v3 = acc[mt][nt][3] + bv[nt][1];
                ob[(size_t)co0 * TS_ + pr]           = v0;
                ob[(size_t)(co0 + 1) * TS_ + pr]     = v1;
                ob[(size_t)co0 * TS_ + pr + 8]       = v2;
                ob[(size_t)(co0 + 1) * TS_ + pr + 8] = v3;
                st_s[nt * 2]     += v0 + v2;
                st_q[nt * 2]     += v0 * v0 + v2 * v2;
                st_s[nt * 2 + 1] += v1 + v3;
                st_q[nt * 2 + 1] += v1 * v1 + v3 * v3;
            }
        }
        __syncthreads();
    }

    // reduce BN0 stats: butterfly over g lanes (bits 2..4 of lane)
#pragma unroll
    for (int i = 0; i < 8; i++) {
        st_s[i] += __shfl_xor_sync(0xffffffffu, st_s[i], 4);
        st_s[i] += __shfl_xor_sync(0xffffffffu, st_s[i], 8);
        st_s[i] += __shfl_xor_sync(0xffffffffu, st_s[i], 16);
        st_q[i] += __shfl_xor_sync(0xffffffffu, st_q[i], 4);
        st_q[i] += __shfl_xor_sync(0xffffffffu, st_q[i], 8);
        st_q[i] += __shfl_xor_sync(0xffffffffu, st_q[i], 16);
    }
    if (lane < 4) {
#pragma unroll
        for (int nt = 0; nt < 4; nt++)
#pragma unroll
            for (int r = 0; r < 2; r++) {
                const int co = nh * 32 + nt * 8 + lane * 2 + r;
                atomicAdd(&s_st[co], st_s[nt * 2 + r]);
                atomicAdd(&s_st[64 + co], st_q[nt * 2 + r]);
            }
    }
    __syncthreads();
    if (tid < 128) atomicAdd(&g_sum0[tid], s_st[tid]);
}

// ---------------- zero accumulators ----------------
__global__ void k_zero() {
    int i = threadIdx.x;
    if (i < 128) { g_sum0[i] = 0.f; g_sum1[i] = 0.f; }
}

// ---------------- BN coefficients ----------------
__global__ void k_coef(int mode, const float* __restrict__ g,
                       const float* __restrict__ beta) {
    const int c = threadIdx.x;
    if (c >= 64) return;
    const float* sums = mode ? g_sum1 : g_sum0;
    float* coef = mode ? g_coef1 : g_coef0;
    const float inv = 1.0f / CNT_;
    float mu = sums[c] * inv;
    float var = sums[64 + c] * inv - mu * mu;
    float A = g[c] * rsqrtf(var + 1e-5f);
    coef[c] = A;
    coef[64 + c] = beta[c] - mu * A;
}

// ---------------- qkv: bf16 mma, M=192, K=64, N=128-pixel tiles ----------------
__global__ void __launch_bounds__(256) k_qkv_mma(const float* __restrict__ bias) {
    __shared__ __nv_bfloat16 Ws[192 * 72];
    __shared__ __nv_bfloat16 Xt[128 * 72];
    const int tid = threadIdx.x, lane = tid & 31, wid = tid >> 5;
    const int j0 = blockIdx.x * 128;
    const int bt = blockIdx.y, b = bt >> 3, t = bt & 7;

    {
        const uint4* src = (const uint4*)g_wqkv;
        for (int e = tid; e < 1536; e += 256) {
            int co = e >> 3, q = e & 7;
            *(uint4*)&Ws[co * 72 + q * 8] = src[e];
        }
    }
    {
        const float* xb = g_x + ((size_t)(b * C_) * T_ + t) * S_ + j0;
        for (int e = tid; e < 4096; e += 256) {
            int kp = e >> 7, n = e & 127;
            int k0 = kp * 2;
            float v0 = lk(fmaf(xb[(size_t)k0 * TS_ + n], g_coef0[k0], g_coef0[64 + k0]));
            float v1 = lk(fmaf(xb[(size_t)(k0 + 1) * TS_ + n], g_coef0[k0 + 1], g_coef0[64 + k0 + 1]));
            *(uint32_t*)&Xt[n * 72 + k0] = packbf(v0, v1);
        }
    }
    __syncthreads();

    const int mg = wid >> 1, nh = wid & 1;
    const int g = lane >> 2, tg = lane & 3;

    float acc[3][8][4];
#pragma unroll
    for (int mt = 0; mt < 3; mt++)
#pragma unroll
        for (int nt = 0; nt < 8; nt++)
#pragma unroll
            for (int i = 0; i < 4; i++) acc[mt][nt][i] = 0.f;

#pragma unroll
    for (int kk = 0; kk < 4; kk++) {
        const int ko = kk * 16 + tg * 2;
        uint32_t A[3][4];
#pragma unroll
        for (int mt = 0; mt < 3; mt++) {
            const int r = mg * 48 + mt * 16;
            A[mt][0] = *(const uint32_t*)&Ws[(r + g) * 72 + ko];
            A[mt][1] = *(const uint32_t*)&Ws[(r + g + 8) * 72 + ko];
            A[mt][2] = *(const uint32_t*)&Ws[(r + g) * 72 + ko + 8];
            A[mt][3] = *(const uint32_t*)&Ws[(r + g + 8) * 72 + ko + 8];
        }
#pragma unroll
        for (int nt = 0; nt < 8; nt++) {
            const int np = nh * 64 + nt * 8 + g;
            uint32_t b0 = *(const uint32_t*)&Xt[np * 72 + ko];
            uint32_t b1 = *(const uint32_t*)&Xt[np * 72 + ko + 8];
#pragma unroll
            for (int mt = 0; mt < 3; mt++)
                mma_bf16(acc[mt][nt], A[mt][0], A[mt][1], A[mt][2], A[mt][3], b0, b1);
        }
    }

    const int ncol = b * S_ + j0 + nh * 64;
#pragma unroll
    for (int mt = 0; mt < 3; mt++) {
        const int co0 = mg * 48 + mt * 16 + g;
#pragma unroll
        for (int r = 0; r < 2; r++) {
            const int co = co0 + r * 8;
            const int z = co >> 6, mo = co & 63;
            const float bb = __ldg(&bias[co]);
            __nv_bfloat16* op = g_qkvh + (size_t)z * QSZ_ + (size_t)(t * 64 + mo) * N_ + ncol;
#pragma unroll
            for (int nt = 0; nt < 8; nt++) {
                uint32_t pk = packbf(acc[mt][nt][r * 2] + bb, acc[mt][nt][r * 2 + 1] + bb);
                *(uint32_t*)&op[nt * 8 + tg * 2] = pk;
            }
        }
    }
}

// ---------------- attention core (bf16 io) ----------------
__global__ void __launch_bounds__(128) k_attn() {
    const int n = blockIdx.x * 128 + threadIdx.x;
    const int hh = blockIdx.y;
    const int cb = hh * 8;
    const __nv_bfloat16* qp = g_qkvh;
    const __nv_bfloat16* kp = g_qkvh + QSZ_;
    const __nv_bfloat16* vp = g_qkvh + 2 * (size_t)QSZ_;

    float kk[8][8], vv[8][8];
#pragma unroll
    for (int tt = 0; tt < 8; tt++)
#pragma unroll
        for (int d = 0; d < 8; d++) {
            const size_t idx = (size_t)(tt * 64 + cb + d) * N_ + n;
            kk[tt][d] = __bfloat162float(kp[idx]);
            vv[tt][d] = __bfloat162float(vp[idx]);
        }
    const float scale = 0.3535533905932738f;
#pragma unroll
    for (int tq = 0; tq < 8; tq++) {
        float q[8];
#pragma unroll
        for (int d = 0; d < 8; d++)
            q[d] = __bfloat162float(qp[(size_t)(tq * 64 + cb + d) * N_ + n]) * scale;
        float s[8];
        float mx = -1e30f;
#pragma unroll
        for (int tt = 0; tt < 8; tt++) {
            float a = 0.f;
#pragma unroll
            for (int d = 0; d < 8; d++) a = fmaf(q[d], kk[tt][d], a);
            s[tt] = a;
            mx = fmaxf(mx, a);
        }
        float sum = 0.f;
#pragma unroll
        for (int tt = 0; tt < 8; tt++) { s[tt] = __expf(s[tt] - mx); sum += s[tt]; }
        const float inv = 1.0f / sum;
#pragma unroll
        for (int d = 0; d < 8; d++) {
            float o = 0.f;
#pragma unroll
            for (int tt = 0; tt < 8; tt++) o = fmaf(s[tt], vv[tt][d], o);
            g_oh[(size_t)(tq * 64 + cb + d) * N_ + n] = __float2bfloat16(o * inv);
        }
    }
}

// ---------------- out_proj: bf16 mma + fused residual + BN1 stats ----------------
__global__ void __launch_bounds__(256) k_outproj_mma(const float* __restrict__ bias) {
    __shared__ __nv_bfloat16 Ws[64 * 72];
    __shared__ __nv_bfloat16 Ot[128 * 72];
    __shared__ float s_st[128];
    const int tid = threadIdx.x, lane = tid & 31, wid = tid >> 5;
    const int j0 = blockIdx.x * 128;
    const int bt = blockIdx.y, b = bt >> 3, t = bt & 7;

    if (tid < 128) s_st[tid] = 0.f;
    {
        const uint4* src = (const uint4*)g_wout;
        for (int e = tid; e < 512; e += 256) {
            int co = e >> 3, q = e & 7;
            *(uint4*)&Ws[co * 72 + q * 8] = src[e];
        }
    }
    {
        const __nv_bfloat16* ob = g_oh + (size_t)(t * 64) * N_ + b * S_ + j0;
        for (int e = tid; e < 4096; e += 256) {
            int kp = e >> 7, n = e & 127;
            int k0 = kp * 2;
            __nv_bfloat162 p;
            p.x = ob[(size_t)k0 * N_ + n];
            p.y = ob[(size_t)(k0 + 1) * N_ + n];
            *(uint32_t*)&Ot[n * 72 + k0] = *(uint32_t*)&p;
        }
    }
    __syncthreads();

    const int mg = wid >> 2, ng = wid & 3;
    const int g = lane >> 2, tg = lane & 3;

    float acc[2][4][4];
#pragma unroll
    for (int mt = 0; mt < 2; mt++)
#pragma unroll
        for (int nt = 0; nt < 4; nt++)
#pragma unroll
            for (int i = 0; i < 4; i++) acc[mt][nt][i] = 0.f;

#pragma unroll
    for (int kk = 0; kk < 4; kk++) {
        const int ko = kk * 16 + tg * 2;
        uint32_t A[2][4];
#pragma unroll
        for (int mt = 0; mt < 2; mt++) {
            const int r = mg * 32 + mt * 16;
            A[mt][0] = *(const uint32_t*)&Ws[(r + g) * 72 + ko];
            A[mt][1] = *(const uint32_t*)&Ws[(r + g + 8) * 72 + ko];
            A[mt][2] = *(const uint32_t*)&Ws[(r + g) * 72 + ko + 8];
            A[mt][3] = *(const uint32_t*)&Ws[(r + g + 8) * 72 + ko + 8];
        }
#pragma unroll
        for (int nt = 0; nt < 4; nt++) {
            const int np = ng * 32 + nt * 8 + g;
            uint32_t b0 = *(const uint32_t*)&Ot[np * 72 + ko];
            uint32_t b1 = *(const uint32_t*)&Ot[np * 72 + ko + 8];
#pragma unroll
            for (int mt = 0; mt < 2; mt++)
                mma_bf16(acc[mt][nt], A[mt][0], A[mt][1], A[mt][2], A[mt][3], b0, b1);
        }
    }

    float ps[2][2], pq[2][2];
#pragma unroll
    for (int mt = 0; mt < 2; mt++)
#pragma unroll
        for (int r = 0; r < 2; r++) { ps[mt][r] = 0.f; pq[mt][r] = 0.f; }

#pragma unroll
    for (int mt = 0; mt < 2; mt++) {
#pragma unroll
        for (int r = 0; r < 2; r++) {
            const int co = mg * 32 + mt * 16 + r * 8 + g;
            const float bb = __ldg(&bias[co]);
            const float A0 = g_coef0[co], B0 = g_coef0[64 + co];
            const size_t rowb = ((size_t)(b * C_ + co) * T_ + t) * S_ + j0;
#pragma unroll
            for (int nt = 0; nt < 4; nt++) {
                const int px = ng * 32 + nt * 8 + tg * 2;
                float2 xv = *(const float2*)&g_x[rowb + px];
                float2 zv;
                zv.x = lk(fmaf(xv.x, A0, B0)) + acc[mt][nt][r * 2] + bb;
                zv.y = lk(fmaf(xv.y, A0, B0)) + acc[mt][nt][r * 2 + 1] + bb;
                *(float2*)&g_z[rowb + px] = zv;
                ps[mt][r] += zv.x + zv.y;
                pq[mt][r] += zv.x * zv.x + zv.y * zv.y;
            }
        }
    }

    // BN1 stats: reduce over tg (lane bits 0..1), then smem, then global
#pragma unroll
    for (int mt = 0; mt < 2; mt++)
#pragma unroll
        for (int r = 0; r < 2; r++) {
            ps[mt][r] += __shfl_xor_sync(0xffffffffu, ps[mt][r], 1);
            ps[mt][r] += __shfl_xor_sync(0xffffffffu, ps[mt][r], 2);
            pq[mt][r] += __shfl_xor_sync(0xffffffffu, pq[mt][r], 1);
            pq[mt][r] += __shfl_xor_sync(0xffffffffu, pq[mt][r], 2);
        }
    if ((lane & 3) == 0) {
#pragma unroll
        for (int mt = 0; mt < 2; mt++)
#pragma unroll
            for (int r = 0; r < 2; r++) {
                const int co = mg * 32 + mt * 16 + r * 8 + g;
                atomicAdd(&s_st[co], ps[mt][r]);
                atomicAdd(&s_st[64 + co], pq[mt][r]);
            }
    }
    __syncthreads();
    if (tid < 128) atomicAdd(&g_sum1[tid], s_st[tid]);
}

// ---------------- spatial mean of leaky(bn1(z)) ----------------
__global__ void __launch_bounds__(256) k_mean() {
    const int bid = blockIdx.x;
    const int c = (bid >> 3) & 63;
    const float A = g_coef1[c], Bv = g_coef1[64 + c];
    const float* p = g_z + (size_t)bid * S_;
    float s = 0.f;
    for (int i = threadIdx.x; i < S_; i += 256)
        s += lk(fmaf(p[i], A, Bv));
#pragma unroll
    for (int off = 16; off; off >>= 1) s += __shfl_down_sync(0xffffffffu, s, off);
    __shared__ float wa[8];
    const int lane = threadIdx.x & 31, wid = threadIdx.x >> 5;
    if (lane == 0) wa[wid] = s;
    __syncthreads();
    if (threadIdx.x == 0) {
        float ts = 0.f;
#pragma unroll
        for (int i = 0; i < 8; i++) ts += wa[i];
        g_m[bid] = ts * (1.0f / (float)S_);
    }
}

// ---------------- per-(b,t) 5x5 kernels ----------------
__global__ void k_kern(const float* __restrict__ w1, const float* __restrict__ b1) {
    const int idx = blockIdx.x * 256 + threadIdx.x;
    if (idx >= B_ * T_ * 25) return;
    const int b = idx / (T_ * 25);
    const int r = idx - b * (T_ * 25);
    const int t = r / 25;
    const int o = r - t * 25;
    float a = b1[o];
#pragma unroll 8
    for (int c = 0; c < 64; c++)
        a = fmaf(g_m[(b * C_ + c) * T_ + t], w1[o * 64 + c], a);
    g_kern[(b * T_ + t) * 25 + o] = a;
}

// ---------------- dynamic depthwise 5x5 conv ----------------
__global__ void __launch_bounds__(256) k_dynconv(const float* __restrict__ h,
                                                 float* __restrict__ out) {
    __shared__ float sp[100 * 100];
    __shared__ float sk[25];
    const int bid = blockIdx.x;
    const int b = bid >> 9;
    const int t = bid & 7;
    const int tid = threadIdx.x;
    const float* base = h + (size_t)bid * S_;

    for (int i = tid; i < 10000; i += 256) sp[i] = 0.f;
    if (tid < 25) sk[tid] = g_kern[(b * T_ + t) * 25 + tid];
    __syncthreads();
    for (int i = tid; i < S_; i += 256) {
        const int r = i / 96, col = i - r * 96;
        sp[(r + 2) * 100 + col + 2] = base[i];
    }
    __syncthreads();

    float kr[25];
#pragma unroll
    for (int q = 0; q < 25; q++) kr[q] = sk[q];

    float* ob = out + (size_t)bid * S_;
    for (int i = tid; i < S_; i += 256) {
        const int r = i / 96, col = i - r * 96;
        const float* pp = &sp[r * 100 + col];
        float a = 0.f;
#pragma unroll
        for (int ii = 0; ii < 5; ii++)
#pragma unroll
            for (int jj = 0; jj < 5; jj++)
                a = fmaf(pp[ii * 100 + jj], kr[ii * 5 + jj], a);
        ob[i] = a;
    }
}

// ---------------- launch ----------------
extern "C" void kernel_launch(void* const* d_in, const int* in_sizes, int n_in,
                              void* d_out, int out_size) {
    const float* h       = (const float*)d_in[0];
    const float* conv0_w = (const float*)d_in[1];
    const float* conv0_b = (const float*)d_in[2];
    const float* bn0_g   = (const float*)d_in[3];
    const float* bn0_b   = (const float*)d_in[4];
    const float* bn1_g   = (const float*)d_in[5];
    const float* bn1_b   = (const float*)d_in[6];
    const float* inW     = (const float*)d_in[7];
    const float* inB     = (const float*)d_in[8];
    const float* outW    = (const float*)d_in[9];
    const float* outB    = (const float*)d_in[10];
    const float* c1w     = (const float*)d_in[11];
    const float* c1b     = (const float*)d_in[12];
    float* out = (float*)d_out;

    cudaFuncSetAttribute(k_conv0_mma, cudaFuncAttributeMaxDynamicSharedMemorySize,
                         SM_CONV_TOT);

    k_zero<<<1, 128>>>();
    k_wprep<<<(64 * 576 + 255) / 256, 256>>>(conv0_w);
    k_wprep2<<<(192 * 64 + 255) / 256, 256>>>(inW, outW);
    k_conv0_mma<<<dim3(4, B_ * T_), 256, SM_CONV_TOT>>>(h, conv0_b);
    k_coef<<<1, 64>>>(0, bn0_g, bn0_b);
    k_qkv_mma<<<dim3(S_ / 128, B_ * T_), 256>>>(inB);
    k_attn<<<dim3(N_ / 128, 8), 128>>>();
    k_outproj_mma<<<dim3(S_ / 128, B_ * T_), 256>>>(outB);
    k_coef<<<1, 64>>>(1, bn1_g, bn1_b);
    k_mean<<<B_ * C_ * T_, 256>>>();
    k_kern<<<4, 256>>>(c1w, c1b);
    k_dynconv<<<B_ * C_ * T_, 256>>>(h, out);
}

// round 7
// speedup vs baseline: 3.1743x; 1.1067x over previous
#include <cuda_runtime.h>
#include <cuda_bf16.h>
#include <cstdint>

// Problem constants
#define B_ 4
#define C_ 64
#define T_ 8
#define X_ 96
#define Y_ 96
#define S_ 9216            // X_*Y_
#define N_ 36864           // B_*S_
#define TS_ 73728          // T_*S_
#define TOTAL_ 18874368    // B_*C_*T_*S_
#define QSZ_ 18874368      // T_*C_*N_
#define CNT_ 294912.0f     // B_*T_*S_

// -------- scratch (device globals; no runtime allocation) --------
__device__ float g_x[TOTAL_];                     // conv0 raw output (pre-BN0)
__device__ __nv_bfloat16 g_qkvh[3 * QSZ_];        // q,k,v bf16, [z][t][c][n]
__device__ __nv_bfloat16 g_oh[QSZ_];              // attention out bf16, [t][c][n]
__device__ __nv_bfloat16 g_zh[TOTAL_];            // residual + out_proj (pre-BN1), bf16
__device__ float g_sum0[128];
__device__ float g_sum1[128];
__device__ float g_coef0[128];                    // bn0: A[0:64], B[64:128]
__device__ float g_coef1[128];
__device__ float g_m[B_ * C_ * T_];
__device__ float g_kern[B_ * T_ * 25];
__device__ __align__(16) __nv_bfloat16 g_wk[64 * 576];   // conv0 [co][k], k=tap*64+ci
__device__ __align__(16) __nv_bfloat16 g_wqkv[192 * 64]; // in_proj bf16
__device__ __align__(16) __nv_bfloat16 g_wout[64 * 64];  // out_proj bf16

__device__ __forceinline__ float lk(float v) { return v >= 0.f ? v : 0.01f * v; }

__device__ __forceinline__ void mma_bf16(float* c, uint32_t a0, uint32_t a1,
                                         uint32_t a2, uint32_t a3,
                                         uint32_t b0, uint32_t b1) {
    asm volatile(
        "mma.sync.aligned.m16n8k16.row.col.f32.bf16.bf16.f32 "
        "{%0,%1,%2,%3}, {%4,%5,%6,%7}, {%8,%9}, {%0,%1,%2,%3};"
        : "+f"(c[0]), "+f"(c[1]), "+f"(c[2]), "+f"(c[3])
        : "r"(a0), "r"(a1), "r"(a2), "r"(a3), "r"(b0), "r"(b1));
}

__device__ __forceinline__ uint32_t packbf(float a, float b) {
    __nv_bfloat162 p = __floats2bfloat162_rn(a, b);
    return *(uint32_t*)&p;
}

// ===================== weight prep =====================
__global__ void k_wprep(const float* __restrict__ w) {
    int i = blockIdx.x * 256 + threadIdx.x;
    if (i >= 64 * 576) return;
    int co = i / 576, k = i - co * 576;
    int tap = k >> 6, ci = k & 63;
    g_wk[i] = __float2bfloat16(w[(co * 64 + ci) * 9 + tap]);
}
__global__ void k_wprep2(const float* __restrict__ inW, const float* __restrict__ outW) {
    int i = blockIdx.x * 256 + threadIdx.x;
    if (i < 192 * 64) g_wqkv[i] = __float2bfloat16(inW[i]);
    if (i < 64 * 64) g_wout[i] = __float2bfloat16(outW[i]);
}

// ===================== conv0: persistent tile-pair bf16 mma, 512 thr =====================
#define SINW 74
#define ROWE (98 * SINW)                // 7252 elems per row slot
#define RING 8
#define WKS 584
#define SM_WK_OFF (RING * ROWE * 2)     // 116032 bytes
#define SM_CONV_TOT (SM_WK_OFF + 64 * WKS * 2)   // 190784 bytes

__device__ __forceinline__ void stage_row(__nv_bfloat16* sin_s, const float* hb,
                                          int gx, int tid) {
    const int slot = (gx + 8) & 7;
    __nv_bfloat16* dst = sin_s + slot * ROWE;
    if ((unsigned)gx >= 96u) {
        for (int e = tid; e < 6144; e += 512) {
            int ci = e / 96, y = e - ci * 96;
            dst[(y + 1) * SINW + ci] = __float2bfloat16(0.f);
        }
    } else {
        const float* hp = hb + (size_t)gx * 96;
        for (int e = tid; e < 6144; e += 512) {
            int ci = e / 96, y = e - ci * 96;
            dst[(y + 1) * SINW + ci] = __float2bfloat16(hp[(size_t)ci * TS_ + y]);
        }
    }
    if (tid < 64) dst[tid] = __float2bfloat16(0.f);
    else if (tid < 128) dst[97 * SINW + (tid - 64)] = __float2bfloat16(0.f);
}

__global__ void __launch_bounds__(512)
k_conv0_mma(const float* __restrict__ h, const float* __restrict__ bias) {
    extern __shared__ char smem[];
    __nv_bfloat16* sin_s = (__nv_bfloat16*)smem;
    __nv_bfloat16* wk_s = (__nv_bfloat16*)(smem + SM_WK_OFF);
    __shared__ float s_st[128];

    const int tid = threadIdx.x, lane = tid & 31, wid = tid >> 5;
    const int group = blockIdx.x, bt = blockIdx.y, b = bt >> 3, t = bt & 7;
    const float* hb = h + (size_t)b * (64 * TS_) + (size_t)t * S_;

    if (tid < 128) s_st[tid] = 0.f;
    // stage weights once
    {
        const uint4* src = (const uint4*)g_wk;
        for (int e = tid; e < 4608; e += 512) {
            int co = e / 72, q = e - co * 72;
            *(uint4*)&wk_s[co * WKS + q * 8] = src[e];
        }
    }
    // prologue: rows for first tile-pair
    {
        const int p0 = group * 2304;
        const int xlo = p0 / 96, xhi = (p0 + 255) / 96;
        for (int gx = xlo - 1; gx <= xhi + 1; gx++) stage_row(sin_s, hb, gx, tid);
    }
    __syncthreads();

    const int mg = wid >> 1, nh = wid & 1;   // mg: 8 pixel groups of 32; nh: co half
    const int g = lane >> 2, tg = lane & 3;

    float bv[4][2];
#pragma unroll
    for (int nt = 0; nt < 4; nt++) {
        const int co0 = nh * 32 + nt * 8 + tg * 2;
        bv[nt][0] = __ldg(&bias[co0]);
        bv[nt][1] = __ldg(&bias[co0 + 1]);
    }

    float st_s[8], st_q[8];
#pragma unroll
    for (int i = 0; i < 8; i++) { st_s[i] = 0.f; st_q[i] = 0.f; }

    float* obB = g_x + (size_t)b * (64 * TS_) + (size_t)t * S_;

    for (int ti = 0; ti < 9; ti++) {
        const int p0 = group * 2304 + ti * 256;
        const int xhi = (p0 + 255) / 96;
        // stage rows for next tile-pair (disjoint ring slots; overlaps compute)
        if (ti < 8) {
            const int xhin = (p0 + 511) / 96;
            for (int gx = xhi + 2; gx <= xhin + 1; gx++) stage_row(sin_s, hb, gx, tid);
        }

        int slotoff[2][2][3];
#pragma unroll
        for (int mt = 0; mt < 2; mt++)
#pragma unroll
            for (int hf = 0; hf < 2; hf++) {
                int p = mg * 32 + mt * 16 + hf * 8 + g;
                int gp = p0 + p, px = gp / 96, py = gp - px * 96;
#pragma unroll
                for (int dx = 0; dx < 3; dx++)
                    slotoff[mt][hf][dx] = ((px + dx - 1 + 8) & 7) * ROWE + py * SINW;
            }

        float acc[2][4][4];
#pragma unroll
        for (int mt = 0; mt < 2; mt++)
#pragma unroll
            for (int nt = 0; nt < 4; nt++)
#pragma unroll
                for (int i = 0; i < 4; i++) acc[mt][nt][i] = 0.f;

#pragma unroll
        for (int tap = 0; tap < 9; tap++) {
            const int dx = tap / 3, dy = tap - dx * 3;
            const int cb = dy * SINW + tg * 2;
#pragma unroll
            for (int kk = 0; kk < 4; kk++) {
                const int ko = kk * 16;
                uint32_t A[2][4];
#pragma unroll
                for (int mt = 0; mt < 2; mt++) {
                    A[mt][0] = *(const uint32_t*)&sin_s[slotoff[mt][0][dx] + cb + ko];
                    A[mt][1] = *(const uint32_t*)&sin_s[slotoff[mt][1][dx] + cb + ko];
                    A[mt][2] = *(const uint32_t*)&sin_s[slotoff[mt][0][dx] + cb + ko + 8];
                    A[mt][3] = *(const uint32_t*)&sin_s[slotoff[mt][1][dx] + cb + ko + 8];
                }
                const int kbase = tap * 64 + ko;
#pragma unroll
                for (int nt = 0; nt < 4; nt++) {
                    const int co = nh * 32 + nt * 8 + g;
                    uint32_t b0 = *(const uint32_t*)&wk_s[co * WKS + kbase + tg * 2];
                    uint32_t b1 = *(const uint32_t*)&wk_s[co * WKS + kbase + 8 + tg * 2];
#pragma unroll
                    for (int mt = 0; mt < 2; mt++)
                        mma_bf16(acc[mt][nt], A[mt][0], A[mt][1], A[mt][2], A[mt][3], b0, b1);
                }
            }
        }

        // writeout + BN0 stats
        float* ob = obB + p0;
#pragma unroll
        for (int nt = 0; nt < 4; nt++) {
            const int co0 = nh * 32 + nt * 8 + tg * 2;
#pragma unroll
            for (int mt = 0; mt < 2; mt++) {
                const int pr = mg * 32 + mt * 16 + g;
                float v0 = acc[mt][nt][0] + bv[nt][0];
                float v1 = acc[mt][nt][1] + bv[nt][1];
                float v2 = acc[mt][nt][2] + bv[nt][0];
                float v3 = acc[mt][nt][3] + bv[nt][1];
                ob[(size_t)co0 * TS_ + pr]           = v0;
                ob[(size_t)(co0 + 1) * TS_ + pr]     = v1;
                ob[(size_t)co0 * TS_ + pr + 8]       = v2;
                ob[(size_t)(co0 + 1) * TS_ + pr + 8] = v3;
                st_s[nt * 2]     += v0 + v2;
                st_q[nt * 2]     += v0 * v0 + v2 * v2;
                st_s[nt * 2 + 1] += v1 + v3;
                st_q[nt * 2 + 1] += v1 * v1 + v3 * v3;
            }
        }
        __syncthreads();
    }

    // BN0 stats reduce: over g lanes (bits 2..4)
#pragma unroll
    for (int i = 0; i < 8; i++) {
        st_s[i] += __shfl_xor_sync(0xffffffffu, st_s[i], 4);
        st_s[i] += __shfl_xor_sync(0xffffffffu, st_s[i], 8);
        st_s[i] += __shfl_xor_sync(0xffffffffu, st_s[i], 16);
        st_q[i] += __shfl_xor_sync(0xffffffffu, st_q[i], 4);
        st_q[i] += __shfl_xor_sync(0xffffffffu, st_q[i], 8);
        st_q[i] += __shfl_xor_sync(0xffffffffu, st_q[i], 16);
    }
    if (lane < 4) {
#pragma unroll
        for (int nt = 0; nt < 4; nt++)
#pragma unroll
            for (int r = 0; r < 2; r++) {
                const int co = nh * 32 + nt * 8 + lane * 2 + r;
                atomicAdd(&s_st[co], st_s[nt * 2 + r]);
                atomicAdd(&s_st[64 + co], st_q[nt * 2 + r]);
            }
    }
    __syncthreads();
    if (tid < 128) atomicAdd(&g_sum0[tid], s_st[tid]);
}

// ---------------- zero accumulators ----------------
__global__ void k_zero() {
    int i = threadIdx.x;
    if (i < 128) { g_sum0[i] = 0.f; g_sum1[i] = 0.f; }
}

// ---------------- BN coefficients ----------------
__global__ void k_coef(int mode, const float* __restrict__ g,
                       const float* __restrict__ beta) {
    const int c = threadIdx.x;
    if (c >= 64) return;
    const float* sums = mode ? g_sum1 : g_sum0;
    float* coef = mode ? g_coef1 : g_coef0;
    const float inv = 1.0f / CNT_;
    float mu = sums[c] * inv;
    float var = sums[64 + c] * inv - mu * mu;
    float A = g[c] * rsqrtf(var + 1e-5f);
    coef[c] = A;
    coef[64 + c] = beta[c] - mu * A;
}

// ---------------- qkv: bf16 mma, M=192, K=64, N=128-pixel tiles ----------------
__global__ void __launch_bounds__(256) k_qkv_mma(const float* __restrict__ bias) {
    __shared__ __nv_bfloat16 Ws[192 * 72];
    __shared__ __nv_bfloat16 Xt[128 * 72];
    const int tid = threadIdx.x, lane = tid & 31, wid = tid >> 5;
    const int j0 = blockIdx.x * 128;
    const int bt = blockIdx.y, b = bt >> 3, t = bt & 7;

    {
        const uint4* src = (const uint4*)g_wqkv;
        for (int e = tid; e < 1536; e += 256) {
            int co = e >> 3, q = e & 7;
            *(uint4*)&Ws[co * 72 + q * 8] = src[e];
        }
    }
    {
        const float* xb = g_x + ((size_t)(b * C_) * T_ + t) * S_ + j0;
        for (int e = tid; e < 4096; e += 256) {
            int kp = e >> 7, n = e & 127;
            int k0 = kp * 2;
            float v0 = lk(fmaf(xb[(size_t)k0 * TS_ + n], g_coef0[k0], g_coef0[64 + k0]));
            float v1 = lk(fmaf(xb[(size_t)(k0 + 1) * TS_ + n], g_coef0[k0 + 1], g_coef0[64 + k0 + 1]));
            *(uint32_t*)&Xt[n * 72 + k0] = packbf(v0, v1);
        }
    }
    __syncthreads();

    const int mg = wid >> 1, nh = wid & 1;
    const int g = lane >> 2, tg = lane & 3;

    float acc[3][8][4];
#pragma unroll
    for (int mt = 0; mt < 3; mt++)
#pragma unroll
        for (int nt = 0; nt < 8; nt++)
#pragma unroll
            for (int i = 0; i < 4; i++) acc[mt][nt][i] = 0.f;

#pragma unroll
    for (int kk = 0; kk < 4; kk++) {
        const int ko = kk * 16 + tg * 2;
        uint32_t A[3][4];
#pragma unroll
        for (int mt = 0; mt < 3; mt++) {
            const int r = mg * 48 + mt * 16;
            A[mt][0] = *(const uint32_t*)&Ws[(r + g) * 72 + ko];
            A[mt][1] = *(const uint32_t*)&Ws[(r + g + 8) * 72 + ko];
            A[mt][2] = *(const uint32_t*)&Ws[(r + g) * 72 + ko + 8];
            A[mt][3] = *(const uint32_t*)&Ws[(r + g + 8) * 72 + ko + 8];
        }
#pragma unroll
        for (int nt = 0; nt < 8; nt++) {
            const int np = nh * 64 + nt * 8 + g;
            uint32_t b0 = *(const uint32_t*)&Xt[np * 72 + ko];
            uint32_t b1 = *(const uint32_t*)&Xt[np * 72 + ko + 8];
#pragma unroll
            for (int mt = 0; mt < 3; mt++)
                mma_bf16(acc[mt][nt], A[mt][0], A[mt][1], A[mt][2], A[mt][3], b0, b1);
        }
    }

    const int ncol = b * S_ + j0 + nh * 64;
#pragma unroll
    for (int mt = 0; mt < 3; mt++) {
        const int co0 = mg * 48 + mt * 16 + g;
#pragma unroll
        for (int r = 0; r < 2; r++) {
            const int co = co0 + r * 8;
            const int z = co >> 6, mo = co & 63;
            const float bb = __ldg(&bias[co]);
            __nv_bfloat16* op = g_qkvh + (size_t)z * QSZ_ + (size_t)(t * 64 + mo) * N_ + ncol;
#pragma unroll
            for (int nt = 0; nt < 8; nt++) {
                uint32_t pk = packbf(acc[mt][nt][r * 2] + bb, acc[mt][nt][r * 2 + 1] + bb);
                *(uint32_t*)&op[nt * 8 + tg * 2] = pk;
            }
        }
    }
}

// ---------------- attention core (bf16 io) ----------------
__global__ void __launch_bounds__(128) k_attn() {
    const int n = blockIdx.x * 128 + threadIdx.x;
    const int hh = blockIdx.y;
    const int cb = hh * 8;
    const __nv_bfloat16* qp = g_qkvh;
    const __nv_bfloat16* kp = g_qkvh + QSZ_;
    const __nv_bfloat16* vp = g_qkvh + 2 * (size_t)QSZ_;

    float kk[8][8], vv[8][8];
#pragma unroll
    for (int tt = 0; tt < 8; tt++)
#pragma unroll
        for (int d = 0; d < 8; d++) {
            const size_t idx = (size_t)(tt * 64 + cb + d) * N_ + n;
            kk[tt][d] = __bfloat162float(kp[idx]);
            vv[tt][d] = __bfloat162float(vp[idx]);
        }
    const float scale = 0.3535533905932738f;
#pragma unroll
    for (int tq = 0; tq < 8; tq++) {
        float q[8];
#pragma unroll
        for (int d = 0; d < 8; d++)
            q[d] = __bfloat162float(qp[(size_t)(tq * 64 + cb + d) * N_ + n]) * scale;
        float s[8];
        float mx = -1e30f;
#pragma unroll
        for (int tt = 0; tt < 8; tt++) {
            float a = 0.f;
#pragma unroll
            for (int d = 0; d < 8; d++) a = fmaf(q[d], kk[tt][d], a);
            s[tt] = a;
            mx = fmaxf(mx, a);
        }
        float sum = 0.f;
#pragma unroll
        for (int tt = 0; tt < 8; tt++) { s[tt] = __expf(s[tt] - mx); sum += s[tt]; }
        const float inv = 1.0f / sum;
#pragma unroll
        for (int d = 0; d < 8; d++) {
            float o = 0.f;
#pragma unroll
            for (int tt = 0; tt < 8; tt++) o = fmaf(s[tt], vv[tt][d], o);
            g_oh[(size_t)(tq * 64 + cb + d) * N_ + n] = __float2bfloat16(o * inv);
        }
    }
}

// ---------------- out_proj: bf16 mma + fused residual + BN1 stats ----------------
__global__ void __launch_bounds__(256) k_outproj_mma(const float* __restrict__ bias) {
    __shared__ __nv_bfloat16 Ws[64 * 72];
    __shared__ __nv_bfloat16 Ot[128 * 72];
    __shared__ float s_st[128];
    const int tid = threadIdx.x, lane = tid & 31, wid = tid >> 5;
    const int j0 = blockIdx.x * 128;
    const int bt = blockIdx.y, b = bt >> 3, t = bt & 7;

    if (tid < 128) s_st[tid] = 0.f;
    {
        const uint4* src = (const uint4*)g_wout;
        for (int e = tid; e < 512; e += 256) {
            int co = e >> 3, q = e & 7;
            *(uint4*)&Ws[co * 72 + q * 8] = src[e];
        }
    }
    {
        const __nv_bfloat16* ob = g_oh + (size_t)(t * 64) * N_ + b * S_ + j0;
        for (int e = tid; e < 4096; e += 256) {
            int kp = e >> 7, n = e & 127;
            int k0 = kp * 2;
            __nv_bfloat162 p;
            p.x = ob[(size_t)k0 * N_ + n];
            p.y = ob[(size_t)(k0 + 1) * N_ + n];
            *(uint32_t*)&Ot[n * 72 + k0] = *(uint32_t*)&p;
        }
    }
    __syncthreads();

    const int mg = wid >> 2, ng = wid & 3;
    const int g = lane >> 2, tg = lane & 3;

    float acc[2][4][4];
#pragma unroll
    for (int mt = 0; mt < 2; mt++)
#pragma unroll
        for (int nt = 0; nt < 4; nt++)
#pragma unroll
            for (int i = 0; i < 4; i++) acc[mt][nt][i] = 0.f;

#pragma unroll
    for (int kk = 0; kk < 4; kk++) {
        const int ko = kk * 16 + tg * 2;
        uint32_t A[2][4];
#pragma unroll
        for (int mt = 0; mt < 2; mt++) {
            const int r = mg * 32 + mt * 16;
            A[mt][0] = *(const uint32_t*)&Ws[(r + g) * 72 + ko];
            A[mt][1] = *(const uint32_t*)&Ws[(r + g + 8) * 72 + ko];
            A[mt][2] = *(const uint32_t*)&Ws[(r + g) * 72 + ko + 8];
            A[mt][3] = *(const uint32_t*)&Ws[(r + g + 8) * 72 + ko + 8];
        }
#pragma unroll
        for (int nt = 0; nt < 4; nt++) {
            const int np = ng * 32 + nt * 8 + g;
            uint32_t b0 = *(const uint32_t*)&Ot[np * 72 + ko];
            uint32_t b1 = *(const uint32_t*)&Ot[np * 72 + ko + 8];
#pragma unroll
            for (int mt = 0; mt < 2; mt++)
                mma_bf16(acc[mt][nt], A[mt][0], A[mt][1], A[mt][2], A[mt][3], b0, b1);
        }
    }

    float ps[2][2], pq[2][2];
#pragma unroll
    for (int mt = 0; mt < 2; mt++)
#pragma unroll
        for (int r = 0; r < 2; r++) { ps[mt][r] = 0.f; pq[mt][r] = 0.f; }

#pragma unroll
    for (int mt = 0; mt < 2; mt++) {
#pragma unroll
        for (int r = 0; r < 2; r++) {
            const int co = mg * 32 + mt * 16 + r * 8 + g;
            const float bb = __ldg(&bias[co]);
            const float A0 = g_coef0[co], B0 = g_coef0[64 + co];
            const size_t rowb = ((size_t)(b * C_ + co) * T_ + t) * S_ + j0;
#pragma unroll
            for (int nt = 0; nt < 4; nt++) {
                const int px = ng * 32 + nt * 8 + tg * 2;
                float2 xv = *(const float2*)&g_x[rowb + px];
                float zx = lk(fmaf(xv.x, A0, B0)) + acc[mt][nt][r * 2] + bb;
                float zy = lk(fmaf(xv.y, A0, B0)) + acc[mt][nt][r * 2 + 1] + bb;
                *(uint32_t*)&g_zh[rowb + px] = packbf(zx, zy);
                ps[mt][r] += zx + zy;
                pq[mt][r] += zx * zx + zy * zy;
            }
        }
    }

#pragma unroll
    for (int mt = 0; mt < 2; mt++)
#pragma unroll
        for (int r = 0; r < 2; r++) {
            ps[mt][r] += __shfl_xor_sync(0xffffffffu, ps[mt][r], 1);
            ps[mt][r] += __shfl_xor_sync(0xffffffffu, ps[mt][r], 2);
            pq[mt][r] += __shfl_xor_sync(0xffffffffu, pq[mt][r], 1);
            pq[mt][r] += __shfl_xor_sync(0xffffffffu, pq[mt][r], 2);
        }
    if ((lane & 3) == 0) {
#pragma unroll
        for (int mt = 0; mt < 2; mt++)
#pragma unroll
            for (int r = 0; r < 2; r++) {
                const int co = mg * 32 + mt * 16 + r * 8 + g;
                atomicAdd(&s_st[co], ps[mt][r]);
                atomicAdd(&s_st[64 + co], pq[mt][r]);
            }
    }
    __syncthreads();
    if (tid < 128) atomicAdd(&g_sum1[tid], s_st[tid]);
}

// ---------------- spatial mean of leaky(bn1(z)), bf16 input ----------------
__global__ void __launch_bounds__(256) k_mean() {
    const int bid = blockIdx.x;
    const int c = (bid >> 3) & 63;
    const float A = g_coef1[c], Bv = g_coef1[64 + c];
    const uint32_t* p = (const uint32_t*)(g_zh + (size_t)bid * S_);
    float s = 0.f;
    for (int i = threadIdx.x; i < S_ / 2; i += 256) {
        uint32_t u = p[i];
        __nv_bfloat162 bp = *(__nv_bfloat162*)&u;
        s += lk(fmaf(__bfloat162float(bp.x), A, Bv));
        s += lk(fmaf(__bfloat162float(bp.y), A, Bv));
    }
#pragma unroll
    for (int off = 16; off; off >>= 1) s += __shfl_down_sync(0xffffffffu, s, off);
    __shared__ float wa[8];
    const int lane = threadIdx.x & 31, wid = threadIdx.x >> 5;
    if (lane == 0) wa[wid] = s;
    __syncthreads();
    if (threadIdx.x == 0) {
        float ts = 0.f;
#pragma unroll
        for (int i = 0; i < 8; i++) ts += wa[i];
        g_m[bid] = ts * (1.0f / (float)S_);
    }
}

// ---------------- per-(b,t) 5x5 kernels ----------------
__global__ void k_kern(const float* __restrict__ w1, const float* __restrict__ b1) {
    const int idx = blockIdx.x * 256 + threadIdx.x;
    if (idx >= B_ * T_ * 25) return;
    const int b = idx / (T_ * 25);
    const int r = idx - b * (T_ * 25);
    const int t = r / 25;
    const int o = r - t * 25;
    float a = b1[o];
#pragma unroll 8
    for (int c = 0; c < 64; c++)
        a = fmaf(g_m[(b * C_ + c) * T_ + t], w1[o * 64 + c], a);
    g_kern[(b * T_ + t) * 25 + o] = a;
}

// ---------------- dynamic depthwise 5x5 conv ----------------
__global__ void __launch_bounds__(256) k_dynconv(const float* __restrict__ h,
                                                 float* __restrict__ out) {
    __shared__ float sp[100 * 100];
    __shared__ float sk[25];
    const int bid = blockIdx.x;
    const int b = bid >> 9;
    const int t = bid & 7;
    const int tid = threadIdx.x;
    const float* base = h + (size_t)bid * S_;

    for (int i = tid; i < 10000; i += 256) sp[i] = 0.f;
    if (tid < 25) sk[tid] = g_kern[(b * T_ + t) * 25 + tid];
    __syncthreads();
    for (int i = tid; i < S_; i += 256) {
        const int r = i / 96, col = i - r * 96;
        sp[(r + 2) * 100 + col + 2] = base[i];
    }
    __syncthreads();

    float kr[25];
#pragma unroll
    for (int q = 0; q < 25; q++) kr[q] = sk[q];

    float* ob = out + (size_t)bid * S_;
    for (int i = tid; i < S_; i += 256) {
        const int r = i / 96, col = i - r * 96;
        const float* pp = &sp[r * 100 + col];
        float a = 0.f;
#pragma unroll
        for (int ii = 0; ii < 5; ii++)
#pragma unroll
            for (int jj = 0; jj < 5; jj++)
                a = fmaf(pp[ii * 100 + jj], kr[ii * 5 + jj], a);
        ob[i] = a;
    }
}

// ---------------- launch ----------------
extern "C" void kernel_launch(void* const* d_in, const int* in_sizes, int n_in,
                              void* d_out, int out_size) {
    const float* h       = (const float*)d_in[0];
    const float* conv0_w = (const float*)d_in[1];
    const float* conv0_b = (const float*)d_in[2];
    const float* bn0_g   = (const float*)d_in[3];
    const float* bn0_b   = (const float*)d_in[4];
    const float* bn1_g   = (const float*)d_in[5];
    const float* bn1_b   = (const float*)d_in[6];
    const float* inW     = (const float*)d_in[7];
    const float* inB     = (const float*)d_in[8];
    const float* outW    = (const float*)d_in[9];
    const float* outB    = (const float*)d_in[10];
    const float* c1w     = (const float*)d_in[11];
    const float* c1b     = (const float*)d_in[12];
    float* out = (float*)d_out;

    cudaFuncSetAttribute(k_conv0_mma, cudaFuncAttributeMaxDynamicSharedMemorySize,
                         SM_CONV_TOT);

    k_zero<<<1, 128>>>();
    k_wprep<<<(64 * 576 + 255) / 256, 256>>>(conv0_w);
    k_wprep2<<<(192 * 64 + 255) / 256, 256>>>(inW, outW);
    k_conv0_mma<<<dim3(4, B_ * T_), 512, SM_CONV_TOT>>>(h, conv0_b);
    k_coef<<<1, 64>>>(0, bn0_g, bn0_b);
    k_qkv_mma<<<dim3(S_ / 128, B_ * T_), 256>>>(inB);
    k_attn<<<dim3(N_ / 128, 8), 128>>>();
    k_outproj_mma<<<dim3(S_ / 128, B_ * T_), 256>>>(outB);
    k_coef<<<1, 64>>>(1, bn1_g, bn1_b);
    k_mean<<<B_ * C_ * T_, 256>>>();
    k_kern<<<4, 256>>>(c1w, c1b);
    k_dynconv<<<B_ * C_ * T_, 256>>>(h, out);
}